// round 12
// baseline (speedup 1.0000x reference)
#include <cuda_runtime.h>
#include <cuda_bf16.h>
#include <cuda_fp16.h>
#include <cstdint>

#define BATCH 4
#define SEQ   2048
#define DMODEL 1024
#define NHEAD 16
#define DHEAD 64
#define MTOT  (BATCH*SEQ)   // 8192

// ---------------- scratch (static device globals; no runtime alloc) ----------
__device__ __nv_bfloat16 g_xb [MTOT*DMODEL];            // x in bf16
__device__ __nv_bfloat16 g_Qb [BATCH*NHEAD*SEQ*DHEAD];  // [B,H,S,DH] bf16
__device__ __nv_bfloat16 g_Kb [BATCH*NHEAD*SEQ*DHEAD];  // bf16
__device__ __half        g_Vh [BATCH*NHEAD*SEQ*DHEAD];  // fp16 (for f16 PV mma)
__device__ __nv_bfloat16 g_ctxb[MTOT*DMODEL];           // attention out, bf16
__device__ __nv_bfloat16 g_Wtb[4*DMODEL*DMODEL];        // transposed bf16 weights
__device__ float         g_h  [MTOT*DMODEL];            // O-proj out, fp32
__device__ float         g_msc[BATCH*SEQ];              // mask * log2(e)

// ---------------- low-level helpers ------------------------------------------
__device__ __forceinline__ uint32_t smem_u32(const void* p) {
    uint32_t a;
    asm("{ .reg .u64 t; cvta.to.shared.u64 t, %1; cvt.u32.u64 %0, t; }" : "=r"(a) : "l"(p));
    return a;
}
__device__ __forceinline__ void cpasync16(uint32_t dst, const void* src) {
    asm volatile("cp.async.cg.shared.global [%0], [%1], 16;" :: "r"(dst), "l"(src));
}
__device__ __forceinline__ void cp_commit() { asm volatile("cp.async.commit_group;"); }
__device__ __forceinline__ void cp_wait0()  { asm volatile("cp.async.wait_group 0;"); }

// pack two f32 -> f16x2 (lo in low half), then exp2 both halves in ONE MUFU op
__device__ __forceinline__ uint32_t ex2_f16x2(float lo, float hi) {
    uint32_t d;
    asm("cvt.rn.f16x2.f32 %0, %1, %2;" : "=r"(d) : "f"(hi), "f"(lo));
    asm("ex2.approx.f16x2 %0, %0;" : "+r"(d));
    return d;
}

__device__ __forceinline__ void mma_bf16(float c[4], const uint32_t a[4],
                                         uint32_t b0, uint32_t b1) {
    asm volatile(
        "mma.sync.aligned.m16n8k16.row.col.f32.bf16.bf16.f32 "
        "{%0,%1,%2,%3}, {%4,%5,%6,%7}, {%8,%9}, {%0,%1,%2,%3};"
        : "+f"(c[0]), "+f"(c[1]), "+f"(c[2]), "+f"(c[3])
        : "r"(a[0]), "r"(a[1]), "r"(a[2]), "r"(a[3]), "r"(b0), "r"(b1));
}
__device__ __forceinline__ void mma_f16(float c[4], const uint32_t a[4],
                                        uint32_t b0, uint32_t b1) {
    asm volatile(
        "mma.sync.aligned.m16n8k16.row.col.f32.f16.f16.f32 "
        "{%0,%1,%2,%3}, {%4,%5,%6,%7}, {%8,%9}, {%0,%1,%2,%3};"
        : "+f"(c[0]), "+f"(c[1]), "+f"(c[2]), "+f"(c[3])
        : "r"(a[0]), "r"(a[1]), "r"(a[2]), "r"(a[3]), "r"(b0), "r"(b1));
}
__device__ __forceinline__ void ldsm_x4(uint32_t& r0, uint32_t& r1,
                                        uint32_t& r2, uint32_t& r3, uint32_t addr) {
    asm volatile("ldmatrix.sync.aligned.m8n8.x4.shared.b16 {%0,%1,%2,%3}, [%4];"
        : "=r"(r0), "=r"(r1), "=r"(r2), "=r"(r3) : "r"(addr));
}
__device__ __forceinline__ void ldsm_x4_t(uint32_t& r0, uint32_t& r1,
                                          uint32_t& r2, uint32_t& r3, uint32_t addr) {
    asm volatile("ldmatrix.sync.aligned.m8n8.x4.trans.shared.b16 {%0,%1,%2,%3}, [%4];"
        : "=r"(r0), "=r"(r1), "=r"(r2), "=r"(r3) : "r"(addr));
}
__device__ __forceinline__ uint32_t pack_bf16(float lo, float hi) {
    __nv_bfloat162 t = __float22bfloat162_rn(make_float2(lo, hi));
    return *reinterpret_cast<uint32_t*>(&t);
}
__device__ __forceinline__ uint32_t pack_f16(float lo, float hi) {
    __half2 t = __floats2half2_rn(lo, hi);
    return *reinterpret_cast<uint32_t*>(&t);
}

// ---------------- fp32 -> bf16 convert ----------------------------------------
__global__ __launch_bounds__(256) void cvt_kernel(
    const float* __restrict__ x, __nv_bfloat162* __restrict__ o)
{
    size_t i = (size_t)blockIdx.x * 256 + threadIdx.x;   // over float4
    float4 v = ((const float4*)x)[i];
    o[2 * i]     = __float22bfloat162_rn(make_float2(v.x, v.y));
    o[2 * i + 1] = __float22bfloat162_rn(make_float2(v.z, v.w));
}

// ---------------- mask prescale: m * log2(e) ----------------------------------
__global__ __launch_bounds__(256) void mask_kernel(
    const float* __restrict__ m, float* __restrict__ o)
{
    int i = blockIdx.x * 256 + threadIdx.x;
    o[i] = m[i] * 1.4426950408889634f;
}

// -------- transpose + convert all 4 weights: W[K][N] fp32 -> Wt[N][K] bf16 ----
__global__ __launch_bounds__(256) void tr_kernel(
    const float* __restrict__ s0, const float* __restrict__ s1,
    const float* __restrict__ s2, const float* __restrict__ s3,
    __nv_bfloat16* __restrict__ dstb)
{
    const float* src = (blockIdx.z == 0) ? s0 : (blockIdx.z == 1) ? s1
                     : (blockIdx.z == 2) ? s2 : s3;
    __nv_bfloat16* dst = dstb + (size_t)blockIdx.z * DMODEL * DMODEL;
    __shared__ float t[32][33];
    int x = blockIdx.x * 32 + threadIdx.x;
    int y = blockIdx.y * 32 + threadIdx.y;
#pragma unroll
    for (int j = 0; j < 32; j += 8)
        t[threadIdx.y + j][threadIdx.x] = src[(size_t)(y + j) * DMODEL + x];
    __syncthreads();
    int x2 = blockIdx.y * 32 + threadIdx.x;
    int y2 = blockIdx.x * 32 + threadIdx.y;
#pragma unroll
    for (int j = 0; j < 32; j += 8)
        dst[(size_t)(y2 + j) * DMODEL + x2] = __float2bfloat16(t[threadIdx.x][threadIdx.y + j]);
}

// ---------------- bf16 GEMM: out = A[M,1024] @ Wt^T + bias --------------------
// R7 shape: BM=BN=128, BK=32, 8 warps (4m x 2n), warp tile 32x64, m16n8k16,
// 2-stage cp.async, static 40KB smem, 2 CTAs/SM. grid.z selects weight/bias/out.
// z==2 (V projection) emits fp16; other split_heads outputs emit bf16.
#define GBM 128
#define GBN 128
#define GBK 32
#define GLD 20                 // words per smem row (16 data + 4 pad)
#define GROWB (GLD*4)          // 80 bytes per row
#define GSTG (128*GLD)         // words per half-stage (A or B)

__global__ __launch_bounds__(256, 2) void gemm_bf16(
    const __nv_bfloat16* __restrict__ A, const __nv_bfloat16* __restrict__ Wt3,
    const float* __restrict__ b0p, const float* __restrict__ b1p,
    const float* __restrict__ b2p,
    void* __restrict__ o0p, void* __restrict__ o1p, void* __restrict__ o2p,
    int split_heads, float scale0)
{
    __shared__ __align__(16) uint32_t gsm[4 * GSTG];   // A0,A1,B0,B1 = 40KB
    const uint32_t sb = smem_u32(gsm);

    const int z = blockIdx.z;
    const __nv_bfloat16* Bt = Wt3 + (size_t)z * DMODEL * DMODEL;
    const float* bias = (z == 0) ? b0p : (z == 1) ? b1p : b2p;
    void* outp        = (z == 0) ? o0p : (z == 1) ? o1p : o2p;
    const float oscale = (z == 0) ? scale0 : 1.0f;
    const int fp16out  = (z == 2);

    const int tid  = threadIdx.x;
    const int lane = tid & 31;
    const int warp = tid >> 5;
    const int wm   = warp >> 1;          // 0..3
    const int wn   = warp & 1;           // 0..1
    const int m0   = blockIdx.y * GBM;
    const int n0   = blockIdx.x * GBN;

    const __nv_bfloat16* Abase = A  + (size_t)m0 * DMODEL;
    const __nv_bfloat16* Bbase = Bt + (size_t)n0 * DMODEL;

    const int lr = lane & 7;
    const uint32_t aoff = (uint32_t)((((lane >> 3) & 1) * 8 + lr) * GROWB
                                     + ((lane >> 4) & 1) * 16);
    const uint32_t boff = (uint32_t)((((lane >> 4) & 1) * 8 + lr) * GROWB
                                     + ((lane >> 3) & 1) * 16);

    float acc[2][8][4];
#pragma unroll
    for (int im = 0; im < 2; im++)
#pragma unroll
        for (int in = 0; in < 8; in++)
#pragma unroll
            for (int k = 0; k < 4; k++) acc[im][in][k] = 0.f;

#define GLOAD(c, s) do {                                                       \
        _Pragma("unroll")                                                      \
        for (int i_ = 0; i_ < 2; i_++) {                                       \
            int idx_ = tid + i_ * 256;                                         \
            int r_ = idx_ >> 2, q_ = idx_ & 3;                                 \
            cpasync16(sb + ((s) * GSTG + r_ * GLD + q_ * 4) * 4,               \
                      Abase + (size_t)r_ * DMODEL + (c) * GBK + q_ * 8);       \
        }                                                                      \
        _Pragma("unroll")                                                      \
        for (int i_ = 0; i_ < 2; i_++) {                                       \
            int idx_ = tid + i_ * 256;                                         \
            int r_ = idx_ >> 2, q_ = idx_ & 3;                                 \
            cpasync16(sb + ((2 + (s)) * GSTG + (r_ * GLD + q_ * 4)) * 4,       \
                      Bbase + (size_t)r_ * DMODEL + (c) * GBK + q_ * 8);       \
        }                                                                      \
        cp_commit();                                                           \
    } while (0)

    GLOAD(0, 0);
    const int NCH = DMODEL / GBK;   // 32
    for (int c = 0; c < NCH; c++) {
        const int bsl = c & 1;
        cp_wait0();
        __syncthreads();
        if (c + 1 < NCH) GLOAD(c + 1, 1 - bsl);

        const uint32_t abase = sb + (uint32_t)(bsl * GSTG * 4)
                             + (uint32_t)(wm * 32) * GROWB + aoff;
        const uint32_t bbase = sb + (uint32_t)((2 + bsl) * GSTG * 4)
                             + (uint32_t)(wn * 64) * GROWB + boff;

#pragma unroll
        for (int ks = 0; ks < 2; ks++) {
            uint32_t a[2][4];
            ldsm_x4(a[0][0], a[0][1], a[0][2], a[0][3], abase + ks * 32);
            ldsm_x4(a[1][0], a[1][1], a[1][2], a[1][3], abase + 16 * GROWB + ks * 32);
#pragma unroll
            for (int p = 0; p < 4; p++) {
                uint32_t b00, b01, b10, b11;
                ldsm_x4(b00, b01, b10, b11, bbase + p * 16 * GROWB + ks * 32);
                mma_bf16(acc[0][2 * p],     a[0], b00, b01);
                mma_bf16(acc[0][2 * p + 1], a[0], b10, b11);
                mma_bf16(acc[1][2 * p],     a[1], b00, b01);
                mma_bf16(acc[1][2 * p + 1], a[1], b10, b11);
            }
        }
        __syncthreads();
    }

    // epilogue
#pragma unroll
    for (int im = 0; im < 2; im++) {
#pragma unroll
        for (int in = 0; in < 8; in++) {
            int row = m0 + wm * 32 + im * 16 + (lane >> 2);
            int col = n0 + wn * 64 + in * 8 + 2 * (lane & 3);
            float b0 = bias[col], b1 = bias[col + 1];
            float v00 = (acc[im][in][0] + b0) * oscale;
            float v01 = (acc[im][in][1] + b1) * oscale;
            float v10 = (acc[im][in][2] + b0) * oscale;
            float v11 = (acc[im][in][3] + b1) * oscale;
            if (split_heads) {
                uint16_t* ob = (uint16_t*)outp;
                int bb = row >> 11, s = row & (SEQ - 1);
                int hh = col >> 6,  d = col & 63;
                size_t base = (((size_t)(bb * NHEAD + hh) * SEQ + s) * DHEAD + d);
                uint32_t p0 = fp16out ? pack_f16(v00, v01) : pack_bf16(v00, v01);
                uint32_t p1 = fp16out ? pack_f16(v10, v11) : pack_bf16(v10, v11);
                *(uint32_t*)(ob + base)              = p0;
                *(uint32_t*)(ob + base + 8 * DHEAD)  = p1;
            } else {
                float* of = (float*)outp;
                size_t base = (size_t)row * DMODEL + col;
                *(float2*)(of + base)                       = make_float2(v00, v01);
                *(float2*)(of + base + (size_t)8 * DMODEL)  = make_float2(v10, v11);
            }
        }
    }
}

// ---------------- flash attention, split-K across warp pairs ------------------
// CTA: (b,h,128-query tile), 512 threads = 16 warps. Warps w and w+8 own the
// SAME 16 query rows; w takes keys [0,32), w+8 takes keys [32,64) of each
// tile -> per-warp K/V smem reads halve (crossbar was the limiter).
// No-max base-2 softmax (additive across splits); partial O and l combined
// through a smem scratch (reuses K/V buffers) after the key loop.
#define AQ 128
#define AROW 144                 // bytes per K/V smem row (128 data + 16 pad)
#define KOFF(s) ((s) * 9216)
#define VOFF(s) (18432 + (s) * 9216)
#define MOFF(s) (36864 + (s) * 256)
#define ASMEM 37376
#define ONE2 0x3C003C00u         // fp16x2 (1.0, 1.0)

__global__ __launch_bounds__(512, 1) void attn_kernel(
    const __nv_bfloat16* __restrict__ Q, const __nv_bfloat16* __restrict__ K,
    const __half* __restrict__ V, const float* __restrict__ mask,
    __nv_bfloat16* __restrict__ ctx)
{
    __shared__ __align__(16) uint8_t smr[ASMEM];
    const uint32_t sb = smem_u32(smr);

    const int tid  = threadIdx.x;
    const int lane = tid & 31;
    const int warp = tid >> 5;          // 0..15
    const int rw   = warp & 7;          // row-group 0..7
    const int kh   = warp >> 3;         // key half 0/1

    const int q0 = blockIdx.x * AQ;
    const int h  = blockIdx.y;
    const int b  = blockIdx.z;

    const __nv_bfloat16* Qp = Q + (((size_t)(b * NHEAD + h) * SEQ + q0) * DHEAD);
    const __nv_bfloat16* Kp = K + ((size_t)(b * NHEAD + h) * SEQ) * DHEAD;
    const __half*        Vp = V + ((size_t)(b * NHEAD + h) * SEQ) * DHEAD;
    const float* Mp = mask + (size_t)b * SEQ;

    // 512 threads: one cp.async each for K (64 rows x 8 float4) and V
#define APREFETCH(kt, s) do {                                                  \
        const int key0_ = (kt) * 64;                                           \
        int r_ = tid >> 3, q_ = tid & 7;                                       \
        cpasync16(sb + KOFF(s) + r_ * AROW + q_ * 16,                          \
                  Kp + (size_t)(key0_ + r_) * DHEAD + q_ * 8);                 \
        cpasync16(sb + VOFF(s) + r_ * AROW + q_ * 16,                          \
                  Vp + (size_t)(key0_ + r_) * DHEAD + q_ * 8);                 \
        if (tid < 16)                                                          \
            cpasync16(sb + MOFF(s) + tid * 16, Mp + key0_ + tid * 4);          \
        cp_commit();                                                           \
    } while (0)

    APREFETCH(0, 0);

    // ---- Q fragments straight from gmem (rows shared by warp pair)
    uint32_t qf[4][4];
    {
        const int r = rw * 16 + (lane >> 2);
#pragma unroll
        for (int ks = 0; ks < 4; ks++) {
            int k0 = ks * 16 + 2 * (lane & 3);
            qf[ks][0] = *(const uint32_t*)(Qp + (size_t)r * DHEAD + k0);
            qf[ks][1] = *(const uint32_t*)(Qp + (size_t)(r + 8) * DHEAD + k0);
            qf[ks][2] = *(const uint32_t*)(Qp + (size_t)r * DHEAD + k0 + 8);
            qf[ks][3] = *(const uint32_t*)(Qp + (size_t)(r + 8) * DHEAD + k0 + 8);
        }
    }

    float oacc[8][4];
#pragma unroll
    for (int in = 0; in < 8; in++)
#pragma unroll
        for (int k = 0; k < 4; k++) oacc[in][k] = 0.f;
    float lacc[4] = {0.f, 0.f, 0.f, 0.f};

    const int lr = lane & 7;
    const uint32_t kloff = (uint32_t)((((lane >> 4) & 1) * 8 + lr) * AROW
                                      + ((lane >> 3) & 1) * 16);
    const uint32_t vlaneoff =
        ((lane & 7) + ((lane & 8) ? 8u : 0u)) * AROW + ((lane & 16) ? 16u : 0u);
    const uint32_t khrow = (uint32_t)(kh * 32) * AROW;   // this warp's key half

    for (int kt = 0; kt < SEQ / 64; kt++) {
        const int bsl = kt & 1;
        cp_wait0();
        __syncthreads();
        if (kt + 1 < SEQ / 64) APREFETCH(kt + 1, 1 - bsl);

        const float*   msk   = (const float*)(smr + MOFF(bsl));
        const uint32_t kbase = sb + KOFF(bsl) + khrow + kloff;
        const uint32_t vbase = sb + VOFF(bsl) + khrow;

        // ---- S = Q @ K_half^T  (16 x 32 per warp)
        float sacc[4][4];
#pragma unroll
        for (int in = 0; in < 4; in++)
#pragma unroll
            for (int k = 0; k < 4; k++) sacc[in][k] = 0.f;

#pragma unroll
        for (int ks = 0; ks < 4; ks++) {
#pragma unroll
            for (int p = 0; p < 2; p++) {
                uint32_t b00, b01, b10, b11;
                ldsm_x4(b00, b01, b10, b11, kbase + p * (16 * AROW) + ks * 32);
                mma_bf16(sacc[2 * p],     qf[ks], b00, b01);
                mma_bf16(sacc[2 * p + 1], qf[ks], b10, b11);
            }
        }

        // ---- mask + no-max base-2 softmax -> fp16 P
        uint32_t pk[4][2];
#pragma unroll
        for (int in = 0; in < 4; in++) {
            int c = kh * 32 + in * 8 + 2 * (lane & 3);
            float mv0 = msk[c], mv1 = msk[c + 1];
            pk[in][0] = ex2_f16x2(sacc[in][0] + mv0, sacc[in][1] + mv1);
            pk[in][1] = ex2_f16x2(sacc[in][2] + mv0, sacc[in][3] + mv1);
        }

        // ---- O += P @ V_half (f16 mma); l += P @ ones
#pragma unroll
        for (int ks = 0; ks < 2; ks++) {
            uint32_t a[4] = { pk[2 * ks][0], pk[2 * ks][1],
                              pk[2 * ks + 1][0], pk[2 * ks + 1][1] };
            mma_f16(lacc, a, ONE2, ONE2);
            uint32_t vk = vbase + (uint32_t)(ks * 16) * AROW + vlaneoff;
#pragma unroll
            for (int gi = 0; gi < 4; gi++) {
                uint32_t b0a, b1a, b0b, b1b;
                ldsm_x4_t(b0a, b1a, b0b, b1b, vk + gi * 32);
                mma_f16(oacc[2 * gi],     a, b0a, b1a);
                mma_f16(oacc[2 * gi + 1], a, b0b, b1b);
            }
        }
    }

    // ---- combine split-K halves via smem scratch, then finalize
    __syncthreads();                      // done reading K/V buffers
    float* scr = (float*)smr;             // 8 warps x 32 lanes x 36 floats
    const int sbase = (rw * 32 + lane) * 36;
    if (kh == 1) {
#pragma unroll
        for (int in = 0; in < 8; in++)
            *(float4*)(scr + sbase + in * 4) = make_float4(
                oacc[in][0], oacc[in][1], oacc[in][2], oacc[in][3]);
        scr[sbase + 32] = lacc[0];
        scr[sbase + 33] = lacc[2];
    }
    __syncthreads();
    if (kh == 0) {
        const int rp = rw * 16 + (lane >> 2);
        const float il0 = 1.f / (lacc[0] + scr[sbase + 32]);
        const float il1 = 1.f / (lacc[2] + scr[sbase + 33]);
#pragma unroll
        for (int in = 0; in < 8; in++) {
            float4 o2 = *(const float4*)(scr + sbase + in * 4);
            int c = in * 8 + 2 * (lane & 3);
            size_t base = ((size_t)b * SEQ + q0 + rp) * DMODEL + h * DHEAD + c;
            *(uint32_t*)(ctx + base) =
                pack_bf16((oacc[in][0] + o2.x) * il0, (oacc[in][1] + o2.y) * il0);
            *(uint32_t*)(ctx + base + (size_t)8 * DMODEL) =
                pack_bf16((oacc[in][2] + o2.z) * il1, (oacc[in][3] + o2.w) * il1);
        }
    }
}

// ---------------- residual + LayerNorm ---------------------------------------
__global__ __launch_bounds__(256) void ln_kernel(
    const float* __restrict__ hbuf, const float* __restrict__ x,
    const float* __restrict__ gamma, const float* __restrict__ beta,
    float* __restrict__ out)
{
    const int row = blockIdx.x;
    const int tid = threadIdx.x;
    const int lane = tid & 31, warp = tid >> 5;

    const float4* hp = (const float4*)(hbuf + (size_t)row * DMODEL);
    const float4* xp = (const float4*)(x + (size_t)row * DMODEL);
    float4 hv = hp[tid], xv = xp[tid];
    float4 y = make_float4(hv.x + xv.x, hv.y + xv.y, hv.z + xv.z, hv.w + xv.w);

    float s  = y.x + y.y + y.z + y.w;
    float sq = y.x * y.x + y.y * y.y + y.z * y.z + y.w * y.w;
#pragma unroll
    for (int o = 16; o; o >>= 1) {
        s  += __shfl_xor_sync(0xffffffffu, s, o);
        sq += __shfl_xor_sync(0xffffffffu, sq, o);
    }
    __shared__ float ss[8], ssq[8];
    if (lane == 0) { ss[warp] = s; ssq[warp] = sq; }
    __syncthreads();
    if (warp == 0) {
        s  = (lane < 8) ? ss[lane]  : 0.f;
        sq = (lane < 8) ? ssq[lane] : 0.f;
#pragma unroll
        for (int o = 4; o; o >>= 1) {
            s  += __shfl_xor_sync(0xffffffffu, s, o);
            sq += __shfl_xor_sync(0xffffffffu, sq, o);
        }
        if (lane == 0) { ss[0] = s; ssq[0] = sq; }
    }
    __syncthreads();
    s = ss[0]; sq = ssq[0];

    const float mu   = s * (1.f / DMODEL);
    const float var  = sq * (1.f / DMODEL) - mu * mu;
    const float rstd = rsqrtf(var + 1e-12f);

    float4 g = ((const float4*)gamma)[tid];
    float4 bt = ((const float4*)beta)[tid];
    float4 o;
    o.x = (y.x - mu) * rstd * g.x + bt.x;
    o.y = (y.y - mu) * rstd * g.y + bt.y;
    o.z = (y.z - mu) * rstd * g.z + bt.z;
    o.w = (y.w - mu) * rstd * g.w + bt.w;
    ((float4*)(out + (size_t)row * DMODEL))[tid] = o;
}

// ---------------- launch ------------------------------------------------------
extern "C" void kernel_launch(void* const* d_in, const int* in_sizes, int n_in,
                              void* d_out, int out_size)
{
    const float* x    = (const float*)d_in[0];
    const float* mask = (const float*)d_in[1];
    const float* Wq   = (const float*)d_in[2];
    const float* bq   = (const float*)d_in[3];
    const float* Wk   = (const float*)d_in[4];
    const float* bk   = (const float*)d_in[5];
    const float* Wv   = (const float*)d_in[6];
    const float* bv   = (const float*)d_in[7];
    const float* Wo   = (const float*)d_in[8];
    const float* bo   = (const float*)d_in[9];
    const float* gam  = (const float*)d_in[10];
    const float* bet  = (const float*)d_in[11];
    float* out = (float*)d_out;

    __nv_bfloat16 *pxb, *pQ, *pK, *pC, *pWt;
    __half *pV;
    float *pH, *pM;
    cudaGetSymbolAddress((void**)&pxb, g_xb);
    cudaGetSymbolAddress((void**)&pQ,  g_Qb);
    cudaGetSymbolAddress((void**)&pK,  g_Kb);
    cudaGetSymbolAddress((void**)&pV,  g_Vh);
    cudaGetSymbolAddress((void**)&pC,  g_ctxb);
    cudaGetSymbolAddress((void**)&pWt, g_Wtb);
    cudaGetSymbolAddress((void**)&pH,  g_h);
    cudaGetSymbolAddress((void**)&pM,  g_msc);
    __nv_bfloat16* Wto = pWt + (size_t)3 * DMODEL * DMODEL;

    cvt_kernel<<<MTOT * DMODEL / 4 / 256, 256>>>(x, (__nv_bfloat162*)pxb);
    mask_kernel<<<BATCH * SEQ / 256, 256>>>(mask, pM);
    tr_kernel<<<dim3(32, 32, 4), dim3(32, 8)>>>(Wq, Wk, Wv, Wo, pWt);

    const float qsc = 0.125f * 1.4426950408889634f;   // fold log2e into Q

    // fused QKV: grid.z picks weight/bias/output (z==2 emits fp16 V)
    gemm_bf16<<<dim3(DMODEL / GBN, MTOT / GBM, 3), 256>>>(
        pxb, pWt, bq, bk, bv, pQ, pK, pV, 1, qsc);

    attn_kernel<<<dim3(SEQ / AQ, NHEAD, BATCH), 512>>>(pQ, pK, pV, pM, pC);

    // O-projection (grid.z=1, weight slot 0 = Wto)
    gemm_bf16<<<dim3(DMODEL / GBN, MTOT / GBM, 1), 256>>>(
        pC, Wto, bo, bo, bo, pH, pH, pH, 0, 1.0f);

    ln_kernel<<<MTOT, 256>>>(pH, x, gam, bet, out);
}

// round 13
// speedup vs baseline: 1.0450x; 1.0450x over previous
#include <cuda_runtime.h>
#include <cuda_bf16.h>
#include <cuda_fp16.h>
#include <cstdint>

#define BATCH 4
#define SEQ   2048
#define DMODEL 1024
#define NHEAD 16
#define DHEAD 64
#define MTOT  (BATCH*SEQ)   // 8192

// ---------------- scratch (static device globals; no runtime alloc) ----------
__device__ __nv_bfloat16 g_xb [MTOT*DMODEL];            // x in bf16
__device__ __nv_bfloat16 g_Qb [BATCH*NHEAD*SEQ*DHEAD];  // [B,H,S,DH] bf16
__device__ __nv_bfloat16 g_Kb [BATCH*NHEAD*SEQ*DHEAD];  // bf16
__device__ __half        g_Vh [BATCH*NHEAD*SEQ*DHEAD];  // fp16 (for f16 PV mma)
__device__ __nv_bfloat16 g_ctxb[MTOT*DMODEL];           // attention out, bf16
__device__ __nv_bfloat16 g_Wtb[4*DMODEL*DMODEL];        // transposed bf16 weights
__device__ float         g_h  [MTOT*DMODEL];            // O-proj out, fp32
__device__ float         g_msc[BATCH*SEQ];              // mask * log2(e)

// ---------------- low-level helpers ------------------------------------------
__device__ __forceinline__ uint32_t smem_u32(const void* p) {
    uint32_t a;
    asm("{ .reg .u64 t; cvta.to.shared.u64 t, %1; cvt.u32.u64 %0, t; }" : "=r"(a) : "l"(p));
    return a;
}
__device__ __forceinline__ void cpasync16(uint32_t dst, const void* src) {
    asm volatile("cp.async.cg.shared.global [%0], [%1], 16;" :: "r"(dst), "l"(src));
}
__device__ __forceinline__ void cp_commit() { asm volatile("cp.async.commit_group;"); }
__device__ __forceinline__ void cp_wait0()  { asm volatile("cp.async.wait_group 0;"); }

// pack two f32 -> f16x2 (lo in low half), then exp2 both halves in ONE MUFU op
__device__ __forceinline__ uint32_t ex2_f16x2(float lo, float hi) {
    uint32_t d;
    asm("cvt.rn.f16x2.f32 %0, %1, %2;" : "=r"(d) : "f"(hi), "f"(lo));
    asm("ex2.approx.f16x2 %0, %0;" : "+r"(d));
    return d;
}

__device__ __forceinline__ void mma_bf16(float c[4], const uint32_t a[4],
                                         uint32_t b0, uint32_t b1) {
    asm volatile(
        "mma.sync.aligned.m16n8k16.row.col.f32.bf16.bf16.f32 "
        "{%0,%1,%2,%3}, {%4,%5,%6,%7}, {%8,%9}, {%0,%1,%2,%3};"
        : "+f"(c[0]), "+f"(c[1]), "+f"(c[2]), "+f"(c[3])
        : "r"(a[0]), "r"(a[1]), "r"(a[2]), "r"(a[3]), "r"(b0), "r"(b1));
}
__device__ __forceinline__ void mma_f16(float c[4], const uint32_t a[4],
                                        uint32_t b0, uint32_t b1) {
    asm volatile(
        "mma.sync.aligned.m16n8k16.row.col.f32.f16.f16.f32 "
        "{%0,%1,%2,%3}, {%4,%5,%6,%7}, {%8,%9}, {%0,%1,%2,%3};"
        : "+f"(c[0]), "+f"(c[1]), "+f"(c[2]), "+f"(c[3])
        : "r"(a[0]), "r"(a[1]), "r"(a[2]), "r"(a[3]), "r"(b0), "r"(b1));
}
__device__ __forceinline__ void ldsm_x4(uint32_t& r0, uint32_t& r1,
                                        uint32_t& r2, uint32_t& r3, uint32_t addr) {
    asm volatile("ldmatrix.sync.aligned.m8n8.x4.shared.b16 {%0,%1,%2,%3}, [%4];"
        : "=r"(r0), "=r"(r1), "=r"(r2), "=r"(r3) : "r"(addr));
}
__device__ __forceinline__ void ldsm_x4_t(uint32_t& r0, uint32_t& r1,
                                          uint32_t& r2, uint32_t& r3, uint32_t addr) {
    asm volatile("ldmatrix.sync.aligned.m8n8.x4.trans.shared.b16 {%0,%1,%2,%3}, [%4];"
        : "=r"(r0), "=r"(r1), "=r"(r2), "=r"(r3) : "r"(addr));
}
__device__ __forceinline__ uint32_t pack_bf16(float lo, float hi) {
    __nv_bfloat162 t = __float22bfloat162_rn(make_float2(lo, hi));
    return *reinterpret_cast<uint32_t*>(&t);
}
__device__ __forceinline__ uint32_t pack_f16(float lo, float hi) {
    __half2 t = __floats2half2_rn(lo, hi);
    return *reinterpret_cast<uint32_t*>(&t);
}

// ---------------- fp32 -> bf16 convert ----------------------------------------
__global__ __launch_bounds__(256) void cvt_kernel(
    const float* __restrict__ x, __nv_bfloat162* __restrict__ o)
{
    size_t i = (size_t)blockIdx.x * 256 + threadIdx.x;   // over float4
    float4 v = ((const float4*)x)[i];
    o[2 * i]     = __float22bfloat162_rn(make_float2(v.x, v.y));
    o[2 * i + 1] = __float22bfloat162_rn(make_float2(v.z, v.w));
}

// ---------------- mask prescale: m * log2(e) ----------------------------------
__global__ __launch_bounds__(256) void mask_kernel(
    const float* __restrict__ m, float* __restrict__ o)
{
    int i = blockIdx.x * 256 + threadIdx.x;
    o[i] = m[i] * 1.4426950408889634f;
}

// -------- transpose + convert all 4 weights: W[K][N] fp32 -> Wt[N][K] bf16 ----
__global__ __launch_bounds__(256) void tr_kernel(
    const float* __restrict__ s0, const float* __restrict__ s1,
    const float* __restrict__ s2, const float* __restrict__ s3,
    __nv_bfloat16* __restrict__ dstb)
{
    const float* src = (blockIdx.z == 0) ? s0 : (blockIdx.z == 1) ? s1
                     : (blockIdx.z == 2) ? s2 : s3;
    __nv_bfloat16* dst = dstb + (size_t)blockIdx.z * DMODEL * DMODEL;
    __shared__ float t[32][33];
    int x = blockIdx.x * 32 + threadIdx.x;
    int y = blockIdx.y * 32 + threadIdx.y;
#pragma unroll
    for (int j = 0; j < 32; j += 8)
        t[threadIdx.y + j][threadIdx.x] = src[(size_t)(y + j) * DMODEL + x];
    __syncthreads();
    int x2 = blockIdx.y * 32 + threadIdx.x;
    int y2 = blockIdx.x * 32 + threadIdx.y;
#pragma unroll
    for (int j = 0; j < 32; j += 8)
        dst[(size_t)(y2 + j) * DMODEL + x2] = __float2bfloat16(t[threadIdx.x][threadIdx.y + j]);
}

// ---------------- bf16 GEMM: out = A[M,1024] @ Wt^T + bias --------------------
// R7 shape: BM=BN=128, BK=32, 8 warps (4m x 2n), warp tile 32x64, m16n8k16,
// 2-stage cp.async, static 40KB smem, 2 CTAs/SM. grid.z selects weight/bias/out.
// z==2 (V projection) emits fp16; other split_heads outputs emit bf16.
#define GBM 128
#define GBN 128
#define GBK 32
#define GLD 20                 // words per smem row (16 data + 4 pad)
#define GROWB (GLD*4)          // 80 bytes per row
#define GSTG (128*GLD)         // words per half-stage (A or B)

__global__ __launch_bounds__(256, 2) void gemm_bf16(
    const __nv_bfloat16* __restrict__ A, const __nv_bfloat16* __restrict__ Wt3,
    const float* __restrict__ b0p, const float* __restrict__ b1p,
    const float* __restrict__ b2p,
    void* __restrict__ o0p, void* __restrict__ o1p, void* __restrict__ o2p,
    int split_heads, float scale0)
{
    __shared__ __align__(16) uint32_t gsm[4 * GSTG];   // A0,A1,B0,B1 = 40KB
    const uint32_t sb = smem_u32(gsm);

    const int z = blockIdx.z;
    const __nv_bfloat16* Bt = Wt3 + (size_t)z * DMODEL * DMODEL;
    const float* bias = (z == 0) ? b0p : (z == 1) ? b1p : b2p;
    void* outp        = (z == 0) ? o0p : (z == 1) ? o1p : o2p;
    const float oscale = (z == 0) ? scale0 : 1.0f;
    const int fp16out  = (z == 2);

    const int tid  = threadIdx.x;
    const int lane = tid & 31;
    const int warp = tid >> 5;
    const int wm   = warp >> 1;          // 0..3
    const int wn   = warp & 1;           // 0..1
    const int m0   = blockIdx.y * GBM;
    const int n0   = blockIdx.x * GBN;

    const __nv_bfloat16* Abase = A  + (size_t)m0 * DMODEL;
    const __nv_bfloat16* Bbase = Bt + (size_t)n0 * DMODEL;

    const int lr = lane & 7;
    const uint32_t aoff = (uint32_t)((((lane >> 3) & 1) * 8 + lr) * GROWB
                                     + ((lane >> 4) & 1) * 16);
    const uint32_t boff = (uint32_t)((((lane >> 4) & 1) * 8 + lr) * GROWB
                                     + ((lane >> 3) & 1) * 16);

    float acc[2][8][4];
#pragma unroll
    for (int im = 0; im < 2; im++)
#pragma unroll
        for (int in = 0; in < 8; in++)
#pragma unroll
            for (int k = 0; k < 4; k++) acc[im][in][k] = 0.f;

#define GLOAD(c, s) do {                                                       \
        _Pragma("unroll")                                                      \
        for (int i_ = 0; i_ < 2; i_++) {                                       \
            int idx_ = tid + i_ * 256;                                         \
            int r_ = idx_ >> 2, q_ = idx_ & 3;                                 \
            cpasync16(sb + ((s) * GSTG + r_ * GLD + q_ * 4) * 4,               \
                      Abase + (size_t)r_ * DMODEL + (c) * GBK + q_ * 8);       \
        }                                                                      \
        _Pragma("unroll")                                                      \
        for (int i_ = 0; i_ < 2; i_++) {                                       \
            int idx_ = tid + i_ * 256;                                         \
            int r_ = idx_ >> 2, q_ = idx_ & 3;                                 \
            cpasync16(sb + ((2 + (s)) * GSTG + (r_ * GLD + q_ * 4)) * 4,       \
                      Bbase + (size_t)r_ * DMODEL + (c) * GBK + q_ * 8);       \
        }                                                                      \
        cp_commit();                                                           \
    } while (0)

    GLOAD(0, 0);
    const int NCH = DMODEL / GBK;   // 32
    for (int c = 0; c < NCH; c++) {
        const int bsl = c & 1;
        cp_wait0();
        __syncthreads();
        if (c + 1 < NCH) GLOAD(c + 1, 1 - bsl);

        const uint32_t abase = sb + (uint32_t)(bsl * GSTG * 4)
                             + (uint32_t)(wm * 32) * GROWB + aoff;
        const uint32_t bbase = sb + (uint32_t)((2 + bsl) * GSTG * 4)
                             + (uint32_t)(wn * 64) * GROWB + boff;

#pragma unroll
        for (int ks = 0; ks < 2; ks++) {
            uint32_t a[2][4];
            ldsm_x4(a[0][0], a[0][1], a[0][2], a[0][3], abase + ks * 32);
            ldsm_x4(a[1][0], a[1][1], a[1][2], a[1][3], abase + 16 * GROWB + ks * 32);
#pragma unroll
            for (int p = 0; p < 4; p++) {
                uint32_t b00, b01, b10, b11;
                ldsm_x4(b00, b01, b10, b11, bbase + p * 16 * GROWB + ks * 32);
                mma_bf16(acc[0][2 * p],     a[0], b00, b01);
                mma_bf16(acc[0][2 * p + 1], a[0], b10, b11);
                mma_bf16(acc[1][2 * p],     a[1], b00, b01);
                mma_bf16(acc[1][2 * p + 1], a[1], b10, b11);
            }
        }
        __syncthreads();
    }

    // epilogue
#pragma unroll
    for (int im = 0; im < 2; im++) {
#pragma unroll
        for (int in = 0; in < 8; in++) {
            int row = m0 + wm * 32 + im * 16 + (lane >> 2);
            int col = n0 + wn * 64 + in * 8 + 2 * (lane & 3);
            float b0 = bias[col], b1 = bias[col + 1];
            float v00 = (acc[im][in][0] + b0) * oscale;
            float v01 = (acc[im][in][1] + b1) * oscale;
            float v10 = (acc[im][in][2] + b0) * oscale;
            float v11 = (acc[im][in][3] + b1) * oscale;
            if (split_heads) {
                uint16_t* ob = (uint16_t*)outp;
                int bb = row >> 11, s = row & (SEQ - 1);
                int hh = col >> 6,  d = col & 63;
                size_t base = (((size_t)(bb * NHEAD + hh) * SEQ + s) * DHEAD + d);
                uint32_t p0 = fp16out ? pack_f16(v00, v01) : pack_bf16(v00, v01);
                uint32_t p1 = fp16out ? pack_f16(v10, v11) : pack_bf16(v10, v11);
                *(uint32_t*)(ob + base)              = p0;
                *(uint32_t*)(ob + base + 8 * DHEAD)  = p1;
            } else {
                float* of = (float*)outp;
                size_t base = (size_t)row * DMODEL + col;
                *(float2*)(of + base)                       = make_float2(v00, v01);
                *(float2*)(of + base + (size_t)8 * DMODEL)  = make_float2(v10, v11);
            }
        }
    }
}

// ---------------- flash attention, 32 query rows per warp ---------------------
// CTA: (b,h,256-query tile), 256 threads = 8 warps; warp w owns rows
// [w*32, w*32+32) = two 16-row mma groups that SHARE each K/V fragment load
// (ldsm per unit work halves; ~24% fewer issue slots). No-max base-2 softmax,
// fp16 P via ex2.f16x2, fp16 V, l via ones-mma. cp.async double-buffered.
#define AQ 256
#define AROW 144                 // bytes per K/V smem row (128 data + 16 pad)
#define KOFF(s) ((s) * 9216)
#define VOFF(s) (18432 + (s) * 9216)
#define MOFF(s) (36864 + (s) * 256)
#define ASMEM 37376
#define ONE2 0x3C003C00u         // fp16x2 (1.0, 1.0)

__global__ __launch_bounds__(256, 1) void attn_kernel(
    const __nv_bfloat16* __restrict__ Q, const __nv_bfloat16* __restrict__ K,
    const __half* __restrict__ V, const float* __restrict__ mask,
    __nv_bfloat16* __restrict__ ctx)
{
    __shared__ __align__(16) uint8_t smr[ASMEM];
    const uint32_t sb = smem_u32(smr);

    const int tid  = threadIdx.x;
    const int lane = tid & 31;
    const int warp = tid >> 5;

    const int q0 = blockIdx.x * AQ;
    const int h  = blockIdx.y;
    const int b  = blockIdx.z;

    const __nv_bfloat16* Qp = Q + (((size_t)(b * NHEAD + h) * SEQ + q0) * DHEAD);
    const __nv_bfloat16* Kp = K + ((size_t)(b * NHEAD + h) * SEQ) * DHEAD;
    const __half*        Vp = V + ((size_t)(b * NHEAD + h) * SEQ) * DHEAD;
    const float* Mp = mask + (size_t)b * SEQ;

#define APREFETCH(kt, s) do {                                                  \
        const int key0_ = (kt) * 64;                                           \
        _Pragma("unroll")                                                      \
        for (int i_ = 0; i_ < 2; i_++) {                                       \
            int idx_ = tid + i_ * 256;                                         \
            int r_ = idx_ >> 3, q_ = idx_ & 7;                                 \
            cpasync16(sb + KOFF(s) + r_ * AROW + q_ * 16,                      \
                      Kp + (size_t)(key0_ + r_) * DHEAD + q_ * 8);             \
        }                                                                      \
        _Pragma("unroll")                                                      \
        for (int i_ = 0; i_ < 2; i_++) {                                       \
            int idx_ = tid + i_ * 256;                                         \
            int r_ = idx_ >> 3, q_ = idx_ & 7;                                 \
            cpasync16(sb + VOFF(s) + r_ * AROW + q_ * 16,                      \
                      Vp + (size_t)(key0_ + r_) * DHEAD + q_ * 8);             \
        }                                                                      \
        if (tid < 16)                                                          \
            cpasync16(sb + MOFF(s) + tid * 16, Mp + key0_ + tid * 4);          \
        cp_commit();                                                           \
    } while (0)

    APREFETCH(0, 0);

    // ---- Q fragments for both 16-row groups, straight from gmem
    uint32_t qf[2][4][4];
#pragma unroll
    for (int g = 0; g < 2; g++) {
        const int r = warp * 32 + g * 16 + (lane >> 2);
#pragma unroll
        for (int ks = 0; ks < 4; ks++) {
            int k0 = ks * 16 + 2 * (lane & 3);
            qf[g][ks][0] = *(const uint32_t*)(Qp + (size_t)r * DHEAD + k0);
            qf[g][ks][1] = *(const uint32_t*)(Qp + (size_t)(r + 8) * DHEAD + k0);
            qf[g][ks][2] = *(const uint32_t*)(Qp + (size_t)r * DHEAD + k0 + 8);
            qf[g][ks][3] = *(const uint32_t*)(Qp + (size_t)(r + 8) * DHEAD + k0 + 8);
        }
    }

    float oacc[2][8][4];
#pragma unroll
    for (int g = 0; g < 2; g++)
#pragma unroll
        for (int in = 0; in < 8; in++)
#pragma unroll
            for (int k = 0; k < 4; k++) oacc[g][in][k] = 0.f;
    float lacc[2][4] = {{0.f,0.f,0.f,0.f},{0.f,0.f,0.f,0.f}};

    const int lr = lane & 7;
    const uint32_t kloff = (uint32_t)((((lane >> 4) & 1) * 8 + lr) * AROW
                                      + ((lane >> 3) & 1) * 16);
    const uint32_t vlaneoff =
        ((lane & 7) + ((lane & 8) ? 8u : 0u)) * AROW + ((lane & 16) ? 16u : 0u);

    for (int kt = 0; kt < SEQ / 64; kt++) {
        const int bsl = kt & 1;
        cp_wait0();
        __syncthreads();
        if (kt + 1 < SEQ / 64) APREFETCH(kt + 1, 1 - bsl);

        const float*   msk   = (const float*)(smr + MOFF(bsl));
        const uint32_t kbase = sb + KOFF(bsl) + kloff;
        const uint32_t vbase = sb + VOFF(bsl);

        // ---- S = Q @ K^T for both groups (K frags loaded once)
        float sacc[2][8][4];
#pragma unroll
        for (int g = 0; g < 2; g++)
#pragma unroll
            for (int in = 0; in < 8; in++)
#pragma unroll
                for (int k = 0; k < 4; k++) sacc[g][in][k] = 0.f;

#pragma unroll
        for (int ks = 0; ks < 4; ks++) {
#pragma unroll
            for (int p = 0; p < 4; p++) {
                uint32_t b00, b01, b10, b11;
                ldsm_x4(b00, b01, b10, b11, kbase + p * (16 * AROW) + ks * 32);
                mma_bf16(sacc[0][2 * p],     qf[0][ks], b00, b01);
                mma_bf16(sacc[0][2 * p + 1], qf[0][ks], b10, b11);
                mma_bf16(sacc[1][2 * p],     qf[1][ks], b00, b01);
                mma_bf16(sacc[1][2 * p + 1], qf[1][ks], b10, b11);
            }
        }

        // ---- mask + no-max base-2 softmax -> fp16 P (both groups)
        uint32_t pk[2][8][2];
#pragma unroll
        for (int in = 0; in < 8; in++) {
            int c = in * 8 + 2 * (lane & 3);
            float mv0 = msk[c], mv1 = msk[c + 1];
#pragma unroll
            for (int g = 0; g < 2; g++) {
                pk[g][in][0] = ex2_f16x2(sacc[g][in][0] + mv0, sacc[g][in][1] + mv1);
                pk[g][in][1] = ex2_f16x2(sacc[g][in][2] + mv0, sacc[g][in][3] + mv1);
            }
        }

        // ---- O += P @ V (V frags loaded once, shared by both groups)
#pragma unroll
        for (int ks = 0; ks < 4; ks++) {
            uint32_t a0[4] = { pk[0][2 * ks][0], pk[0][2 * ks][1],
                               pk[0][2 * ks + 1][0], pk[0][2 * ks + 1][1] };
            uint32_t a1[4] = { pk[1][2 * ks][0], pk[1][2 * ks][1],
                               pk[1][2 * ks + 1][0], pk[1][2 * ks + 1][1] };
            mma_f16(lacc[0], a0, ONE2, ONE2);
            mma_f16(lacc[1], a1, ONE2, ONE2);
            uint32_t vk = vbase + (uint32_t)(ks * 16) * AROW + vlaneoff;
#pragma unroll
            for (int gi = 0; gi < 4; gi++) {
                uint32_t b0a, b1a, b0b, b1b;
                ldsm_x4_t(b0a, b1a, b0b, b1b, vk + gi * 32);
                mma_f16(oacc[0][2 * gi],     a0, b0a, b1a);
                mma_f16(oacc[0][2 * gi + 1], a0, b0b, b1b);
                mma_f16(oacc[1][2 * gi],     a1, b0a, b1a);
                mma_f16(oacc[1][2 * gi + 1], a1, b0b, b1b);
            }
        }
    }

    // ---- finalize: /l, write ctx bf16 [B,S,D]
#pragma unroll
    for (int g = 0; g < 2; g++) {
        const int rp = warp * 32 + g * 16 + (lane >> 2);
        const float il0 = 1.f / lacc[g][0];
        const float il1 = 1.f / lacc[g][2];
#pragma unroll
        for (int in = 0; in < 8; in++) {
            int c = in * 8 + 2 * (lane & 3);
            size_t base = ((size_t)b * SEQ + q0 + rp) * DMODEL + h * DHEAD + c;
            *(uint32_t*)(ctx + base) =
                pack_bf16(oacc[g][in][0] * il0, oacc[g][in][1] * il0);
            *(uint32_t*)(ctx + base + (size_t)8 * DMODEL) =
                pack_bf16(oacc[g][in][2] * il1, oacc[g][in][3] * il1);
        }
    }
}

// ---------------- residual + LayerNorm ---------------------------------------
__global__ __launch_bounds__(256) void ln_kernel(
    const float* __restrict__ hbuf, const float* __restrict__ x,
    const float* __restrict__ gamma, const float* __restrict__ beta,
    float* __restrict__ out)
{
    const int row = blockIdx.x;
    const int tid = threadIdx.x;
    const int lane = tid & 31, warp = tid >> 5;

    const float4* hp = (const float4*)(hbuf + (size_t)row * DMODEL);
    const float4* xp = (const float4*)(x + (size_t)row * DMODEL);
    float4 hv = hp[tid], xv = xp[tid];
    float4 y = make_float4(hv.x + xv.x, hv.y + xv.y, hv.z + xv.z, hv.w + xv.w);

    float s  = y.x + y.y + y.z + y.w;
    float sq = y.x * y.x + y.y * y.y + y.z * y.z + y.w * y.w;
#pragma unroll
    for (int o = 16; o; o >>= 1) {
        s  += __shfl_xor_sync(0xffffffffu, s, o);
        sq += __shfl_xor_sync(0xffffffffu, sq, o);
    }
    __shared__ float ss[8], ssq[8];
    if (lane == 0) { ss[warp] = s; ssq[warp] = sq; }
    __syncthreads();
    if (warp == 0) {
        s  = (lane < 8) ? ss[lane]  : 0.f;
        sq = (lane < 8) ? ssq[lane] : 0.f;
#pragma unroll
        for (int o = 4; o; o >>= 1) {
            s  += __shfl_xor_sync(0xffffffffu, s, o);
            sq += __shfl_xor_sync(0xffffffffu, sq, o);
        }
        if (lane == 0) { ss[0] = s; ssq[0] = sq; }
    }
    __syncthreads();
    s = ss[0]; sq = ssq[0];

    const float mu   = s * (1.f / DMODEL);
    const float var  = sq * (1.f / DMODEL) - mu * mu;
    const float rstd = rsqrtf(var + 1e-12f);

    float4 g = ((const float4*)gamma)[tid];
    float4 bt = ((const float4*)beta)[tid];
    float4 o;
    o.x = (y.x - mu) * rstd * g.x + bt.x;
    o.y = (y.y - mu) * rstd * g.y + bt.y;
    o.z = (y.z - mu) * rstd * g.z + bt.z;
    o.w = (y.w - mu) * rstd * g.w + bt.w;
    ((float4*)(out + (size_t)row * DMODEL))[tid] = o;
}

// ---------------- launch ------------------------------------------------------
extern "C" void kernel_launch(void* const* d_in, const int* in_sizes, int n_in,
                              void* d_out, int out_size)
{
    const float* x    = (const float*)d_in[0];
    const float* mask = (const float*)d_in[1];
    const float* Wq   = (const float*)d_in[2];
    const float* bq   = (const float*)d_in[3];
    const float* Wk   = (const float*)d_in[4];
    const float* bk   = (const float*)d_in[5];
    const float* Wv   = (const float*)d_in[6];
    const float* bv   = (const float*)d_in[7];
    const float* Wo   = (const float*)d_in[8];
    const float* bo   = (const float*)d_in[9];
    const float* gam  = (const float*)d_in[10];
    const float* bet  = (const float*)d_in[11];
    float* out = (float*)d_out;

    __nv_bfloat16 *pxb, *pQ, *pK, *pC, *pWt;
    __half *pV;
    float *pH, *pM;
    cudaGetSymbolAddress((void**)&pxb, g_xb);
    cudaGetSymbolAddress((void**)&pQ,  g_Qb);
    cudaGetSymbolAddress((void**)&pK,  g_Kb);
    cudaGetSymbolAddress((void**)&pV,  g_Vh);
    cudaGetSymbolAddress((void**)&pC,  g_ctxb);
    cudaGetSymbolAddress((void**)&pWt, g_Wtb);
    cudaGetSymbolAddress((void**)&pH,  g_h);
    cudaGetSymbolAddress((void**)&pM,  g_msc);
    __nv_bfloat16* Wto = pWt + (size_t)3 * DMODEL * DMODEL;

    cvt_kernel<<<MTOT * DMODEL / 4 / 256, 256>>>(x, (__nv_bfloat162*)pxb);
    mask_kernel<<<BATCH * SEQ / 256, 256>>>(mask, pM);
    tr_kernel<<<dim3(32, 32, 4), dim3(32, 8)>>>(Wq, Wk, Wv, Wo, pWt);

    const float qsc = 0.125f * 1.4426950408889634f;   // fold log2e into Q

    // fused QKV: grid.z picks weight/bias/output (z==2 emits fp16 V)
    gemm_bf16<<<dim3(DMODEL / GBN, MTOT / GBM, 3), 256>>>(
        pxb, pWt, bq, bk, bv, pQ, pK, pV, 1, qsc);

    attn_kernel<<<dim3(SEQ / AQ, NHEAD, BATCH), 256>>>(pQ, pK, pV, pM, pC);

    // O-projection (grid.z=1, weight slot 0 = Wto)
    gemm_bf16<<<dim3(DMODEL / GBN, MTOT / GBM, 1), 256>>>(
        pC, Wto, bo, bo, bo, pH, pH, pH, 0, 1.0f);

    ln_kernel<<<MTOT, 256>>>(pH, x, gam, bet, out);
}

// round 14
// speedup vs baseline: 1.0591x; 1.0135x over previous
#include <cuda_runtime.h>
#include <cuda_bf16.h>
#include <cuda_fp16.h>
#include <cstdint>

#define BATCH 4
#define SEQ   2048
#define DMODEL 1024
#define NHEAD 16
#define DHEAD 64
#define MTOT  (BATCH*SEQ)   // 8192

// ---------------- scratch (static device globals; no runtime alloc) ----------
__device__ __nv_bfloat16 g_xb [MTOT*DMODEL];            // x in bf16
__device__ __nv_bfloat16 g_Qb [BATCH*NHEAD*SEQ*DHEAD];  // [B,H,S,DH] bf16
__device__ __nv_bfloat16 g_Kb [BATCH*NHEAD*SEQ*DHEAD];  // bf16
__device__ __half        g_Vh [BATCH*NHEAD*SEQ*DHEAD];  // fp16 (for f16 PV mma)
__device__ __nv_bfloat16 g_ctxb[MTOT*DMODEL];           // attention out, bf16
__device__ __nv_bfloat16 g_Wtb[4*DMODEL*DMODEL];        // transposed bf16 weights
__device__ float         g_h  [MTOT*DMODEL];            // O-proj out, fp32
__device__ float         g_msc[BATCH*SEQ];              // mask * log2(e)

// ---------------- low-level helpers ------------------------------------------
__device__ __forceinline__ uint32_t smem_u32(const void* p) {
    uint32_t a;
    asm("{ .reg .u64 t; cvta.to.shared.u64 t, %1; cvt.u32.u64 %0, t; }" : "=r"(a) : "l"(p));
    return a;
}
__device__ __forceinline__ void cpasync16(uint32_t dst, const void* src) {
    asm volatile("cp.async.cg.shared.global [%0], [%1], 16;" :: "r"(dst), "l"(src));
}
__device__ __forceinline__ void cp_commit() { asm volatile("cp.async.commit_group;"); }
__device__ __forceinline__ void cp_wait0()  { asm volatile("cp.async.wait_group 0;"); }

// pack two f32 -> f16x2 (lo in low half), then exp2 both halves in ONE MUFU op
__device__ __forceinline__ uint32_t ex2_f16x2(float lo, float hi) {
    uint32_t d;
    asm("cvt.rn.f16x2.f32 %0, %1, %2;" : "=r"(d) : "f"(hi), "f"(lo));
    asm("ex2.approx.f16x2 %0, %0;" : "+r"(d));
    return d;
}

__device__ __forceinline__ void mma_bf16(float c[4], const uint32_t a[4],
                                         uint32_t b0, uint32_t b1) {
    asm volatile(
        "mma.sync.aligned.m16n8k16.row.col.f32.bf16.bf16.f32 "
        "{%0,%1,%2,%3}, {%4,%5,%6,%7}, {%8,%9}, {%0,%1,%2,%3};"
        : "+f"(c[0]), "+f"(c[1]), "+f"(c[2]), "+f"(c[3])
        : "r"(a[0]), "r"(a[1]), "r"(a[2]), "r"(a[3]), "r"(b0), "r"(b1));
}
__device__ __forceinline__ void mma_f16(float c[4], const uint32_t a[4],
                                        uint32_t b0, uint32_t b1) {
    asm volatile(
        "mma.sync.aligned.m16n8k16.row.col.f32.f16.f16.f32 "
        "{%0,%1,%2,%3}, {%4,%5,%6,%7}, {%8,%9}, {%0,%1,%2,%3};"
        : "+f"(c[0]), "+f"(c[1]), "+f"(c[2]), "+f"(c[3])
        : "r"(a[0]), "r"(a[1]), "r"(a[2]), "r"(a[3]), "r"(b0), "r"(b1));
}
__device__ __forceinline__ void ldsm_x4(uint32_t& r0, uint32_t& r1,
                                        uint32_t& r2, uint32_t& r3, uint32_t addr) {
    asm volatile("ldmatrix.sync.aligned.m8n8.x4.shared.b16 {%0,%1,%2,%3}, [%4];"
        : "=r"(r0), "=r"(r1), "=r"(r2), "=r"(r3) : "r"(addr));
}
__device__ __forceinline__ void ldsm_x4_t(uint32_t& r0, uint32_t& r1,
                                          uint32_t& r2, uint32_t& r3, uint32_t addr) {
    asm volatile("ldmatrix.sync.aligned.m8n8.x4.trans.shared.b16 {%0,%1,%2,%3}, [%4];"
        : "=r"(r0), "=r"(r1), "=r"(r2), "=r"(r3) : "r"(addr));
}
__device__ __forceinline__ uint32_t pack_bf16(float lo, float hi) {
    __nv_bfloat162 t = __float22bfloat162_rn(make_float2(lo, hi));
    return *reinterpret_cast<uint32_t*>(&t);
}
__device__ __forceinline__ uint32_t pack_f16(float lo, float hi) {
    __half2 t = __floats2half2_rn(lo, hi);
    return *reinterpret_cast<uint32_t*>(&t);
}

// ---------------- fp32 -> bf16 convert (+ fused mask prescale) ----------------
__global__ __launch_bounds__(256) void cvt_kernel(
    const float* __restrict__ x, __nv_bfloat162* __restrict__ o,
    const float* __restrict__ mask, float* __restrict__ msc)
{
    size_t i = (size_t)blockIdx.x * 256 + threadIdx.x;   // over float4
    float4 v = ((const float4*)x)[i];
    o[2 * i]     = __float22bfloat162_rn(make_float2(v.x, v.y));
    o[2 * i + 1] = __float22bfloat162_rn(make_float2(v.z, v.w));
    if (i < BATCH * SEQ)
        msc[i] = mask[i] * 1.4426950408889634f;
}

// -------- transpose + convert all 4 weights: W[K][N] fp32 -> Wt[N][K] bf16 ----
__global__ __launch_bounds__(256) void tr_kernel(
    const float* __restrict__ s0, const float* __restrict__ s1,
    const float* __restrict__ s2, const float* __restrict__ s3,
    __nv_bfloat16* __restrict__ dstb)
{
    const float* src = (blockIdx.z == 0) ? s0 : (blockIdx.z == 1) ? s1
                     : (blockIdx.z == 2) ? s2 : s3;
    __nv_bfloat16* dst = dstb + (size_t)blockIdx.z * DMODEL * DMODEL;
    __shared__ float t[32][33];
    int x = blockIdx.x * 32 + threadIdx.x;
    int y = blockIdx.y * 32 + threadIdx.y;
#pragma unroll
    for (int j = 0; j < 32; j += 8)
        t[threadIdx.y + j][threadIdx.x] = src[(size_t)(y + j) * DMODEL + x];
    __syncthreads();
    int x2 = blockIdx.y * 32 + threadIdx.x;
    int y2 = blockIdx.x * 32 + threadIdx.y;
#pragma unroll
    for (int j = 0; j < 32; j += 8)
        dst[(size_t)(y2 + j) * DMODEL + x2] = __float2bfloat16(t[threadIdx.x][threadIdx.y + j]);
}

// ---------------- bf16 GEMM: out = A[M,1024] @ Wt^T + bias --------------------
// R7 shape: BM=BN=128, BK=32, 8 warps (4m x 2n), warp tile 32x64, m16n8k16,
// 2-stage cp.async, static 40KB smem, 2 CTAs/SM. grid.z selects weight/bias/out.
// z==2 (V projection) emits fp16; other split_heads outputs emit bf16.
#define GBM 128
#define GBN 128
#define GBK 32
#define GLD 20                 // words per smem row (16 data + 4 pad)
#define GROWB (GLD*4)          // 80 bytes per row
#define GSTG (128*GLD)         // words per half-stage (A or B)

__global__ __launch_bounds__(256, 2) void gemm_bf16(
    const __nv_bfloat16* __restrict__ A, const __nv_bfloat16* __restrict__ Wt3,
    const float* __restrict__ b0p, const float* __restrict__ b1p,
    const float* __restrict__ b2p,
    void* __restrict__ o0p, void* __restrict__ o1p, void* __restrict__ o2p,
    int split_heads, float scale0)
{
    __shared__ __align__(16) uint32_t gsm[4 * GSTG];   // A0,A1,B0,B1 = 40KB
    const uint32_t sb = smem_u32(gsm);

    const int z = blockIdx.z;
    const __nv_bfloat16* Bt = Wt3 + (size_t)z * DMODEL * DMODEL;
    const float* bias = (z == 0) ? b0p : (z == 1) ? b1p : b2p;
    void* outp        = (z == 0) ? o0p : (z == 1) ? o1p : o2p;
    const float oscale = (z == 0) ? scale0 : 1.0f;
    const int fp16out  = (z == 2);

    const int tid  = threadIdx.x;
    const int lane = tid & 31;
    const int warp = tid >> 5;
    const int wm   = warp >> 1;          // 0..3
    const int wn   = warp & 1;           // 0..1
    const int m0   = blockIdx.y * GBM;
    const int n0   = blockIdx.x * GBN;

    const __nv_bfloat16* Abase = A  + (size_t)m0 * DMODEL;
    const __nv_bfloat16* Bbase = Bt + (size_t)n0 * DMODEL;

    const int lr = lane & 7;
    const uint32_t aoff = (uint32_t)((((lane >> 3) & 1) * 8 + lr) * GROWB
                                     + ((lane >> 4) & 1) * 16);
    const uint32_t boff = (uint32_t)((((lane >> 4) & 1) * 8 + lr) * GROWB
                                     + ((lane >> 3) & 1) * 16);

    float acc[2][8][4];
#pragma unroll
    for (int im = 0; im < 2; im++)
#pragma unroll
        for (int in = 0; in < 8; in++)
#pragma unroll
            for (int k = 0; k < 4; k++) acc[im][in][k] = 0.f;

#define GLOAD(c, s) do {                                                       \
        _Pragma("unroll")                                                      \
        for (int i_ = 0; i_ < 2; i_++) {                                       \
            int idx_ = tid + i_ * 256;                                         \
            int r_ = idx_ >> 2, q_ = idx_ & 3;                                 \
            cpasync16(sb + ((s) * GSTG + r_ * GLD + q_ * 4) * 4,               \
                      Abase + (size_t)r_ * DMODEL + (c) * GBK + q_ * 8);       \
        }                                                                      \
        _Pragma("unroll")                                                      \
        for (int i_ = 0; i_ < 2; i_++) {                                       \
            int idx_ = tid + i_ * 256;                                         \
            int r_ = idx_ >> 2, q_ = idx_ & 3;                                 \
            cpasync16(sb + ((2 + (s)) * GSTG + (r_ * GLD + q_ * 4)) * 4,       \
                      Bbase + (size_t)r_ * DMODEL + (c) * GBK + q_ * 8);       \
        }                                                                      \
        cp_commit();                                                           \
    } while (0)

    GLOAD(0, 0);
    const int NCH = DMODEL / GBK;   // 32
    for (int c = 0; c < NCH; c++) {
        const int bsl = c & 1;
        cp_wait0();
        __syncthreads();
        if (c + 1 < NCH) GLOAD(c + 1, 1 - bsl);

        const uint32_t abase = sb + (uint32_t)(bsl * GSTG * 4)
                             + (uint32_t)(wm * 32) * GROWB + aoff;
        const uint32_t bbase = sb + (uint32_t)((2 + bsl) * GSTG * 4)
                             + (uint32_t)(wn * 64) * GROWB + boff;

#pragma unroll
        for (int ks = 0; ks < 2; ks++) {
            uint32_t a[2][4];
            ldsm_x4(a[0][0], a[0][1], a[0][2], a[0][3], abase + ks * 32);
            ldsm_x4(a[1][0], a[1][1], a[1][2], a[1][3], abase + 16 * GROWB + ks * 32);
#pragma unroll
            for (int p = 0; p < 4; p++) {
                uint32_t b00, b01, b10, b11;
                ldsm_x4(b00, b01, b10, b11, bbase + p * 16 * GROWB + ks * 32);
                mma_bf16(acc[0][2 * p],     a[0], b00, b01);
                mma_bf16(acc[0][2 * p + 1], a[0], b10, b11);
                mma_bf16(acc[1][2 * p],     a[1], b00, b01);
                mma_bf16(acc[1][2 * p + 1], a[1], b10, b11);
            }
        }
        __syncthreads();
    }

    // epilogue
#pragma unroll
    for (int im = 0; im < 2; im++) {
#pragma unroll
        for (int in = 0; in < 8; in++) {
            int row = m0 + wm * 32 + im * 16 + (lane >> 2);
            int col = n0 + wn * 64 + in * 8 + 2 * (lane & 3);
            float b0 = bias[col], b1 = bias[col + 1];
            float v00 = (acc[im][in][0] + b0) * oscale;
            float v01 = (acc[im][in][1] + b1) * oscale;
            float v10 = (acc[im][in][2] + b0) * oscale;
            float v11 = (acc[im][in][3] + b1) * oscale;
            if (split_heads) {
                uint16_t* ob = (uint16_t*)outp;
                int bb = row >> 11, s = row & (SEQ - 1);
                int hh = col >> 6,  d = col & 63;
                size_t base = (((size_t)(bb * NHEAD + hh) * SEQ + s) * DHEAD + d);
                uint32_t p0 = fp16out ? pack_f16(v00, v01) : pack_bf16(v00, v01);
                uint32_t p1 = fp16out ? pack_f16(v10, v11) : pack_bf16(v10, v11);
                *(uint32_t*)(ob + base)              = p0;
                *(uint32_t*)(ob + base + 8 * DHEAD)  = p1;
            } else {
                float* of = (float*)outp;
                size_t base = (size_t)row * DMODEL + col;
                *(float2*)(of + base)                       = make_float2(v00, v01);
                *(float2*)(of + base + (size_t)8 * DMODEL)  = make_float2(v10, v11);
            }
        }
    }
}

// ---------------- flash attention (R11 shape, 128-key tiles) ------------------
// CTA: (b,h,128-query tile), 256 threads = 8 warps x 16 rows, full 64-key
// width per warp, TWO 64-key halves per loop iteration (one barrier pair per
// 128 keys instead of per 64). Register footprint identical to R11.
// No-max base-2 softmax, fp16 P via ex2.f16x2, fp16 V, l via ones-mma.
#define AQ 128
#define AROW 144                  // bytes per K/V smem row (128 data + 16 pad)
#define KTSZ (128*AROW)           // 18432 B per K (or V) stage
#define AKOFF(s) ((s) * KTSZ)
#define AVOFF(s) (2 * KTSZ + (s) * KTSZ)
#define AMOFF(s) (4 * KTSZ + (s) * 512)
#define ASMEM (4 * KTSZ + 1024)   // 74752 B
#define ONE2 0x3C003C00u          // fp16x2 (1.0, 1.0)

__global__ __launch_bounds__(256) void attn_kernel(
    const __nv_bfloat16* __restrict__ Q, const __nv_bfloat16* __restrict__ K,
    const __half* __restrict__ V, const float* __restrict__ mask,
    __nv_bfloat16* __restrict__ ctx)
{
    extern __shared__ __align__(16) uint8_t smr[];
    const uint32_t sb = smem_u32(smr);

    const int tid  = threadIdx.x;
    const int lane = tid & 31;
    const int warp = tid >> 5;

    const int q0 = blockIdx.x * AQ;
    const int h  = blockIdx.y;
    const int b  = blockIdx.z;

    const __nv_bfloat16* Qp = Q + (((size_t)(b * NHEAD + h) * SEQ + q0) * DHEAD);
    const __nv_bfloat16* Kp = K + ((size_t)(b * NHEAD + h) * SEQ) * DHEAD;
    const __half*        Vp = V + ((size_t)(b * NHEAD + h) * SEQ) * DHEAD;
    const float* Mp = mask + (size_t)b * SEQ;

    // 128 key rows per stage: 1024 K-f4 + 1024 V-f4 over 256 threads
#define APREFETCH(kt, s) do {                                                  \
        const int key0_ = (kt) * 128;                                          \
        _Pragma("unroll")                                                      \
        for (int i_ = 0; i_ < 4; i_++) {                                       \
            int idx_ = tid + i_ * 256;                                         \
            int r_ = idx_ >> 3, q_ = idx_ & 7;                                 \
            cpasync16(sb + AKOFF(s) + r_ * AROW + q_ * 16,                     \
                      Kp + (size_t)(key0_ + r_) * DHEAD + q_ * 8);             \
            cpasync16(sb + AVOFF(s) + r_ * AROW + q_ * 16,                     \
                      Vp + (size_t)(key0_ + r_) * DHEAD + q_ * 8);             \
        }                                                                      \
        if (tid < 32)                                                          \
            cpasync16(sb + AMOFF(s) + tid * 16, Mp + key0_ + tid * 4);         \
        cp_commit();                                                           \
    } while (0)

    APREFETCH(0, 0);

    // ---- Q fragments straight from gmem (bf16 pairs are mma-native)
    uint32_t qf[4][4];
    {
        const int r = warp * 16 + (lane >> 2);
#pragma unroll
        for (int ks = 0; ks < 4; ks++) {
            int k0 = ks * 16 + 2 * (lane & 3);
            qf[ks][0] = *(const uint32_t*)(Qp + (size_t)r * DHEAD + k0);
            qf[ks][1] = *(const uint32_t*)(Qp + (size_t)(r + 8) * DHEAD + k0);
            qf[ks][2] = *(const uint32_t*)(Qp + (size_t)r * DHEAD + k0 + 8);
            qf[ks][3] = *(const uint32_t*)(Qp + (size_t)(r + 8) * DHEAD + k0 + 8);
        }
    }

    float oacc[8][4];
#pragma unroll
    for (int in = 0; in < 8; in++)
#pragma unroll
        for (int k = 0; k < 4; k++) oacc[in][k] = 0.f;
    float lacc[4] = {0.f, 0.f, 0.f, 0.f};

    const int lr = lane & 7;
    const uint32_t kloff = (uint32_t)((((lane >> 4) & 1) * 8 + lr) * AROW
                                      + ((lane >> 3) & 1) * 16);
    const uint32_t vlaneoff =
        ((lane & 7) + ((lane & 8) ? 8u : 0u)) * AROW + ((lane & 16) ? 16u : 0u);

    for (int kt = 0; kt < SEQ / 128; kt++) {
        const int bsl = kt & 1;
        cp_wait0();
        __syncthreads();
        if (kt + 1 < SEQ / 128) APREFETCH(kt + 1, 1 - bsl);

#pragma unroll
        for (int half = 0; half < 2; half++) {
            const float*   msk   = (const float*)(smr + AMOFF(bsl)) + half * 64;
            const uint32_t hrow  = (uint32_t)(half * 64) * AROW;
            const uint32_t kbase = sb + AKOFF(bsl) + hrow + kloff;
            const uint32_t vbase = sb + AVOFF(bsl) + hrow;

            // ---- S = Q @ K^T  (16 x 64 per warp, registers)
            float sacc[8][4];
#pragma unroll
            for (int in = 0; in < 8; in++)
#pragma unroll
                for (int k = 0; k < 4; k++) sacc[in][k] = 0.f;

#pragma unroll
            for (int ks = 0; ks < 4; ks++) {
#pragma unroll
                for (int p = 0; p < 4; p++) {
                    uint32_t b00, b01, b10, b11;
                    ldsm_x4(b00, b01, b10, b11, kbase + p * (16 * AROW) + ks * 32);
                    mma_bf16(sacc[2 * p],     qf[ks], b00, b01);
                    mma_bf16(sacc[2 * p + 1], qf[ks], b10, b11);
                }
            }

            // ---- mask + no-max base-2 softmax -> fp16 P
            uint32_t pk[8][2];
#pragma unroll
            for (int in = 0; in < 8; in++) {
                int c = in * 8 + 2 * (lane & 3);
                float mv0 = msk[c], mv1 = msk[c + 1];
                pk[in][0] = ex2_f16x2(sacc[in][0] + mv0, sacc[in][1] + mv1);
                pk[in][1] = ex2_f16x2(sacc[in][2] + mv0, sacc[in][3] + mv1);
            }

            // ---- O += P @ V (f16 mma); l += P @ ones
#pragma unroll
            for (int ks = 0; ks < 4; ks++) {
                uint32_t a[4] = { pk[2 * ks][0], pk[2 * ks][1],
                                  pk[2 * ks + 1][0], pk[2 * ks + 1][1] };
                mma_f16(lacc, a, ONE2, ONE2);
                uint32_t vk = vbase + (uint32_t)(ks * 16) * AROW + vlaneoff;
#pragma unroll
                for (int gi = 0; gi < 4; gi++) {
                    uint32_t b0a, b1a, b0b, b1b;
                    ldsm_x4_t(b0a, b1a, b0b, b1b, vk + gi * 32);
                    mma_f16(oacc[2 * gi],     a, b0a, b1a);
                    mma_f16(oacc[2 * gi + 1], a, b0b, b1b);
                }
            }
        }
    }

    // ---- finalize: /l, write ctx bf16 [B,S,D]
    {
        const int rp = warp * 16 + (lane >> 2);
        const float il0 = 1.f / lacc[0];
        const float il1 = 1.f / lacc[2];
#pragma unroll
        for (int in = 0; in < 8; in++) {
            int c = in * 8 + 2 * (lane & 3);
            size_t base = ((size_t)b * SEQ + q0 + rp) * DMODEL + h * DHEAD + c;
            *(uint32_t*)(ctx + base) =
                pack_bf16(oacc[in][0] * il0, oacc[in][1] * il0);
            *(uint32_t*)(ctx + base + (size_t)8 * DMODEL) =
                pack_bf16(oacc[in][2] * il1, oacc[in][3] * il1);
        }
    }
}

// ---------------- residual + LayerNorm ---------------------------------------
__global__ __launch_bounds__(256) void ln_kernel(
    const float* __restrict__ hbuf, const float* __restrict__ x,
    const float* __restrict__ gamma, const float* __restrict__ beta,
    float* __restrict__ out)
{
    const int row = blockIdx.x;
    const int tid = threadIdx.x;
    const int lane = tid & 31, warp = tid >> 5;

    const float4* hp = (const float4*)(hbuf + (size_t)row * DMODEL);
    const float4* xp = (const float4*)(x + (size_t)row * DMODEL);
    float4 hv = hp[tid], xv = xp[tid];
    float4 y = make_float4(hv.x + xv.x, hv.y + xv.y, hv.z + xv.z, hv.w + xv.w);

    float s  = y.x + y.y + y.z + y.w;
    float sq = y.x * y.x + y.y * y.y + y.z * y.z + y.w * y.w;
#pragma unroll
    for (int o = 16; o; o >>= 1) {
        s  += __shfl_xor_sync(0xffffffffu, s, o);
        sq += __shfl_xor_sync(0xffffffffu, sq, o);
    }
    __shared__ float ss[8], ssq[8];
    if (lane == 0) { ss[warp] = s; ssq[warp] = sq; }
    __syncthreads();
    if (warp == 0) {
        s  = (lane < 8) ? ss[lane]  : 0.f;
        sq = (lane < 8) ? ssq[lane] : 0.f;
#pragma unroll
        for (int o = 4; o; o >>= 1) {
            s  += __shfl_xor_sync(0xffffffffu, s, o);
            sq += __shfl_xor_sync(0xffffffffu, sq, o);
        }
        if (lane == 0) { ss[0] = s; ssq[0] = sq; }
    }
    __syncthreads();
    s = ss[0]; sq = ssq[0];

    const float mu   = s * (1.f / DMODEL);
    const float var  = sq * (1.f / DMODEL) - mu * mu;
    const float rstd = rsqrtf(var + 1e-12f);

    float4 g = ((const float4*)gamma)[tid];
    float4 bt = ((const float4*)beta)[tid];
    float4 o;
    o.x = (y.x - mu) * rstd * g.x + bt.x;
    o.y = (y.y - mu) * rstd * g.y + bt.y;
    o.z = (y.z - mu) * rstd * g.z + bt.z;
    o.w = (y.w - mu) * rstd * g.w + bt.w;
    ((float4*)(out + (size_t)row * DMODEL))[tid] = o;
}

// ---------------- launch ------------------------------------------------------
extern "C" void kernel_launch(void* const* d_in, const int* in_sizes, int n_in,
                              void* d_out, int out_size)
{
    const float* x    = (const float*)d_in[0];
    const float* mask = (const float*)d_in[1];
    const float* Wq   = (const float*)d_in[2];
    const float* bq   = (const float*)d_in[3];
    const float* Wk   = (const float*)d_in[4];
    const float* bk   = (const float*)d_in[5];
    const float* Wv   = (const float*)d_in[6];
    const float* bv   = (const float*)d_in[7];
    const float* Wo   = (const float*)d_in[8];
    const float* bo   = (const float*)d_in[9];
    const float* gam  = (const float*)d_in[10];
    const float* bet  = (const float*)d_in[11];
    float* out = (float*)d_out;

    __nv_bfloat16 *pxb, *pQ, *pK, *pC, *pWt;
    __half *pV;
    float *pH, *pM;
    cudaGetSymbolAddress((void**)&pxb, g_xb);
    cudaGetSymbolAddress((void**)&pQ,  g_Qb);
    cudaGetSymbolAddress((void**)&pK,  g_Kb);
    cudaGetSymbolAddress((void**)&pV,  g_Vh);
    cudaGetSymbolAddress((void**)&pC,  g_ctxb);
    cudaGetSymbolAddress((void**)&pWt, g_Wtb);
    cudaGetSymbolAddress((void**)&pH,  g_h);
    cudaGetSymbolAddress((void**)&pM,  g_msc);
    __nv_bfloat16* Wto = pWt + (size_t)3 * DMODEL * DMODEL;

    cvt_kernel<<<MTOT * DMODEL / 4 / 256, 256>>>(x, (__nv_bfloat162*)pxb, mask, pM);
    tr_kernel<<<dim3(32, 32, 4), dim3(32, 8)>>>(Wq, Wk, Wv, Wo, pWt);

    const float qsc = 0.125f * 1.4426950408889634f;   // fold log2e into Q

    // fused QKV: grid.z picks weight/bias/output (z==2 emits fp16 V)
    gemm_bf16<<<dim3(DMODEL / GBN, MTOT / GBM, 3), 256>>>(
        pxb, pWt, bq, bk, bv, pQ, pK, pV, 1, qsc);

    cudaFuncSetAttribute(attn_kernel, cudaFuncAttributeMaxDynamicSharedMemorySize, ASMEM);
    attn_kernel<<<dim3(SEQ / AQ, NHEAD, BATCH), 256, ASMEM>>>(pQ, pK, pV, pM, pC);

    // O-projection (grid.z=1, weight slot 0 = Wto)
    gemm_bf16<<<dim3(DMODEL / GBN, MTOT / GBM, 1), 256>>>(
        pC, Wto, bo, bo, bo, pH, pH, pH, 0, 1.0f);

    ln_kernel<<<MTOT, 256>>>(pH, x, gam, bet, out);
}

// round 15
// speedup vs baseline: 1.0697x; 1.0100x over previous
#include <cuda_runtime.h>
#include <cuda_bf16.h>
#include <cuda_fp16.h>
#include <cstdint>

#define BATCH 4
#define SEQ   2048
#define DMODEL 1024
#define NHEAD 16
#define DHEAD 64
#define MTOT  (BATCH*SEQ)   // 8192

// ---------------- scratch (static device globals; no runtime alloc) ----------
__device__ __nv_bfloat16 g_xb [MTOT*DMODEL];            // x in bf16
__device__ __nv_bfloat16 g_Qb [BATCH*NHEAD*SEQ*DHEAD];  // [B,H,S,DH] bf16
__device__ __nv_bfloat16 g_Kb [BATCH*NHEAD*SEQ*DHEAD];  // bf16
__device__ __half        g_Vh [BATCH*NHEAD*SEQ*DHEAD];  // fp16 (for f16 PV mma)
__device__ __nv_bfloat16 g_ctxb[MTOT*DMODEL];           // attention out, bf16
__device__ __nv_bfloat16 g_Wtb[4*DMODEL*DMODEL];        // transposed bf16 weights
__device__ float         g_h  [MTOT*DMODEL];            // O-proj out, fp32
__device__ float         g_msc[BATCH*SEQ];              // mask * log2(e)

// ---------------- low-level helpers ------------------------------------------
__device__ __forceinline__ uint32_t smem_u32(const void* p) {
    uint32_t a;
    asm("{ .reg .u64 t; cvta.to.shared.u64 t, %1; cvt.u32.u64 %0, t; }" : "=r"(a) : "l"(p));
    return a;
}
__device__ __forceinline__ void cpasync16(uint32_t dst, const void* src) {
    asm volatile("cp.async.cg.shared.global [%0], [%1], 16;" :: "r"(dst), "l"(src));
}
__device__ __forceinline__ void cp_commit() { asm volatile("cp.async.commit_group;"); }
__device__ __forceinline__ void cp_wait0()  { asm volatile("cp.async.wait_group 0;"); }

// pack two f32 -> f16x2 (lo in low half), then exp2 both halves in ONE MUFU op
__device__ __forceinline__ uint32_t ex2_f16x2(float lo, float hi) {
    uint32_t d;
    asm("cvt.rn.f16x2.f32 %0, %1, %2;" : "=r"(d) : "f"(hi), "f"(lo));
    asm("ex2.approx.f16x2 %0, %0;" : "+r"(d));
    return d;
}

__device__ __forceinline__ void mma_bf16(float c[4], const uint32_t a[4],
                                         uint32_t b0, uint32_t b1) {
    asm volatile(
        "mma.sync.aligned.m16n8k16.row.col.f32.bf16.bf16.f32 "
        "{%0,%1,%2,%3}, {%4,%5,%6,%7}, {%8,%9}, {%0,%1,%2,%3};"
        : "+f"(c[0]), "+f"(c[1]), "+f"(c[2]), "+f"(c[3])
        : "r"(a[0]), "r"(a[1]), "r"(a[2]), "r"(a[3]), "r"(b0), "r"(b1));
}
__device__ __forceinline__ void mma_f16(float c[4], const uint32_t a[4],
                                        uint32_t b0, uint32_t b1) {
    asm volatile(
        "mma.sync.aligned.m16n8k16.row.col.f32.f16.f16.f32 "
        "{%0,%1,%2,%3}, {%4,%5,%6,%7}, {%8,%9}, {%0,%1,%2,%3};"
        : "+f"(c[0]), "+f"(c[1]), "+f"(c[2]), "+f"(c[3])
        : "r"(a[0]), "r"(a[1]), "r"(a[2]), "r"(a[3]), "r"(b0), "r"(b1));
}
__device__ __forceinline__ void ldsm_x4(uint32_t& r0, uint32_t& r1,
                                        uint32_t& r2, uint32_t& r3, uint32_t addr) {
    asm volatile("ldmatrix.sync.aligned.m8n8.x4.shared.b16 {%0,%1,%2,%3}, [%4];"
        : "=r"(r0), "=r"(r1), "=r"(r2), "=r"(r3) : "r"(addr));
}
__device__ __forceinline__ void ldsm_x4_t(uint32_t& r0, uint32_t& r1,
                                          uint32_t& r2, uint32_t& r3, uint32_t addr) {
    asm volatile("ldmatrix.sync.aligned.m8n8.x4.trans.shared.b16 {%0,%1,%2,%3}, [%4];"
        : "=r"(r0), "=r"(r1), "=r"(r2), "=r"(r3) : "r"(addr));
}
__device__ __forceinline__ uint32_t pack_bf16(float lo, float hi) {
    __nv_bfloat162 t = __float22bfloat162_rn(make_float2(lo, hi));
    return *reinterpret_cast<uint32_t*>(&t);
}
__device__ __forceinline__ uint32_t pack_f16(float lo, float hi) {
    __half2 t = __floats2half2_rn(lo, hi);
    return *reinterpret_cast<uint32_t*>(&t);
}

// ---------------- fp32 -> bf16 convert (+ fused mask prescale) ----------------
__global__ __launch_bounds__(256) void cvt_kernel(
    const float* __restrict__ x, __nv_bfloat162* __restrict__ o,
    const float* __restrict__ mask, float* __restrict__ msc)
{
    size_t i = (size_t)blockIdx.x * 256 + threadIdx.x;   // over float4
    float4 v = ((const float4*)x)[i];
    o[2 * i]     = __float22bfloat162_rn(make_float2(v.x, v.y));
    o[2 * i + 1] = __float22bfloat162_rn(make_float2(v.z, v.w));
    if (i < BATCH * SEQ)
        msc[i] = mask[i] * 1.4426950408889634f;
}

// -------- transpose + convert all 4 weights: W[K][N] fp32 -> Wt[N][K] bf16 ----
__global__ __launch_bounds__(256) void tr_kernel(
    const float* __restrict__ s0, const float* __restrict__ s1,
    const float* __restrict__ s2, const float* __restrict__ s3,
    __nv_bfloat16* __restrict__ dstb)
{
    const float* src = (blockIdx.z == 0) ? s0 : (blockIdx.z == 1) ? s1
                     : (blockIdx.z == 2) ? s2 : s3;
    __nv_bfloat16* dst = dstb + (size_t)blockIdx.z * DMODEL * DMODEL;
    __shared__ float t[32][33];
    int x = blockIdx.x * 32 + threadIdx.x;
    int y = blockIdx.y * 32 + threadIdx.y;
#pragma unroll
    for (int j = 0; j < 32; j += 8)
        t[threadIdx.y + j][threadIdx.x] = src[(size_t)(y + j) * DMODEL + x];
    __syncthreads();
    int x2 = blockIdx.y * 32 + threadIdx.x;
    int y2 = blockIdx.x * 32 + threadIdx.y;
#pragma unroll
    for (int j = 0; j < 32; j += 8)
        dst[(size_t)(y2 + j) * DMODEL + x2] = __float2bfloat16(t[threadIdx.x][threadIdx.y + j]);
}

// ---------------- bf16 GEMM: out = A[M,1024] @ Wt^T + bias --------------------
// R7 shape: BM=BN=128, BK=32, 8 warps (4m x 2n), warp tile 32x64, m16n8k16,
// 2-stage cp.async, static 40KB smem, 2 CTAs/SM. grid.z selects weight/bias/out.
// z==2 (V projection) emits fp16; other split_heads outputs emit bf16.
#define GBM 128
#define GBN 128
#define GBK 32
#define GLD 20                 // words per smem row (16 data + 4 pad)
#define GROWB (GLD*4)          // 80 bytes per row
#define GSTG (128*GLD)         // words per half-stage (A or B)

__global__ __launch_bounds__(256, 2) void gemm_bf16(
    const __nv_bfloat16* __restrict__ A, const __nv_bfloat16* __restrict__ Wt3,
    const float* __restrict__ b0p, const float* __restrict__ b1p,
    const float* __restrict__ b2p,
    void* __restrict__ o0p, void* __restrict__ o1p, void* __restrict__ o2p,
    int split_heads, float scale0)
{
    __shared__ __align__(16) uint32_t gsm[4 * GSTG];   // A0,A1,B0,B1 = 40KB
    const uint32_t sb = smem_u32(gsm);

    const int z = blockIdx.z;
    const __nv_bfloat16* Bt = Wt3 + (size_t)z * DMODEL * DMODEL;
    const float* bias = (z == 0) ? b0p : (z == 1) ? b1p : b2p;
    void* outp        = (z == 0) ? o0p : (z == 1) ? o1p : o2p;
    const float oscale = (z == 0) ? scale0 : 1.0f;
    const int fp16out  = (z == 2);

    const int tid  = threadIdx.x;
    const int lane = tid & 31;
    const int warp = tid >> 5;
    const int wm   = warp >> 1;          // 0..3
    const int wn   = warp & 1;           // 0..1
    const int m0   = blockIdx.y * GBM;
    const int n0   = blockIdx.x * GBN;

    const __nv_bfloat16* Abase = A  + (size_t)m0 * DMODEL;
    const __nv_bfloat16* Bbase = Bt + (size_t)n0 * DMODEL;

    const int lr = lane & 7;
    const uint32_t aoff = (uint32_t)((((lane >> 3) & 1) * 8 + lr) * GROWB
                                     + ((lane >> 4) & 1) * 16);
    const uint32_t boff = (uint32_t)((((lane >> 4) & 1) * 8 + lr) * GROWB
                                     + ((lane >> 3) & 1) * 16);

    float acc[2][8][4];
#pragma unroll
    for (int im = 0; im < 2; im++)
#pragma unroll
        for (int in = 0; in < 8; in++)
#pragma unroll
            for (int k = 0; k < 4; k++) acc[im][in][k] = 0.f;

#define GLOAD(c, s) do {                                                       \
        _Pragma("unroll")                                                      \
        for (int i_ = 0; i_ < 2; i_++) {                                       \
            int idx_ = tid + i_ * 256;                                         \
            int r_ = idx_ >> 2, q_ = idx_ & 3;                                 \
            cpasync16(sb + ((s) * GSTG + r_ * GLD + q_ * 4) * 4,               \
                      Abase + (size_t)r_ * DMODEL + (c) * GBK + q_ * 8);       \
        }                                                                      \
        _Pragma("unroll")                                                      \
        for (int i_ = 0; i_ < 2; i_++) {                                       \
            int idx_ = tid + i_ * 256;                                         \
            int r_ = idx_ >> 2, q_ = idx_ & 3;                                 \
            cpasync16(sb + ((2 + (s)) * GSTG + (r_ * GLD + q_ * 4)) * 4,       \
                      Bbase + (size_t)r_ * DMODEL + (c) * GBK + q_ * 8);       \
        }                                                                      \
        cp_commit();                                                           \
    } while (0)

    GLOAD(0, 0);
    const int NCH = DMODEL / GBK;   // 32
    for (int c = 0; c < NCH; c++) {
        const int bsl = c & 1;
        cp_wait0();
        __syncthreads();
        if (c + 1 < NCH) GLOAD(c + 1, 1 - bsl);

        const uint32_t abase = sb + (uint32_t)(bsl * GSTG * 4)
                             + (uint32_t)(wm * 32) * GROWB + aoff;
        const uint32_t bbase = sb + (uint32_t)((2 + bsl) * GSTG * 4)
                             + (uint32_t)(wn * 64) * GROWB + boff;

#pragma unroll
        for (int ks = 0; ks < 2; ks++) {
            uint32_t a[2][4];
            ldsm_x4(a[0][0], a[0][1], a[0][2], a[0][3], abase + ks * 32);
            ldsm_x4(a[1][0], a[1][1], a[1][2], a[1][3], abase + 16 * GROWB + ks * 32);
#pragma unroll
            for (int p = 0; p < 4; p++) {
                uint32_t b00, b01, b10, b11;
                ldsm_x4(b00, b01, b10, b11, bbase + p * 16 * GROWB + ks * 32);
                mma_bf16(acc[0][2 * p],     a[0], b00, b01);
                mma_bf16(acc[0][2 * p + 1], a[0], b10, b11);
                mma_bf16(acc[1][2 * p],     a[1], b00, b01);
                mma_bf16(acc[1][2 * p + 1], a[1], b10, b11);
            }
        }
        __syncthreads();
    }

    // epilogue
#pragma unroll
    for (int im = 0; im < 2; im++) {
#pragma unroll
        for (int in = 0; in < 8; in++) {
            int row = m0 + wm * 32 + im * 16 + (lane >> 2);
            int col = n0 + wn * 64 + in * 8 + 2 * (lane & 3);
            float b0 = bias[col], b1 = bias[col + 1];
            float v00 = (acc[im][in][0] + b0) * oscale;
            float v01 = (acc[im][in][1] + b1) * oscale;
            float v10 = (acc[im][in][2] + b0) * oscale;
            float v11 = (acc[im][in][3] + b1) * oscale;
            if (split_heads) {
                uint16_t* ob = (uint16_t*)outp;
                int bb = row >> 11, s = row & (SEQ - 1);
                int hh = col >> 6,  d = col & 63;
                size_t base = (((size_t)(bb * NHEAD + hh) * SEQ + s) * DHEAD + d);
                uint32_t p0 = fp16out ? pack_f16(v00, v01) : pack_bf16(v00, v01);
                uint32_t p1 = fp16out ? pack_f16(v10, v11) : pack_bf16(v10, v11);
                *(uint32_t*)(ob + base)              = p0;
                *(uint32_t*)(ob + base + 8 * DHEAD)  = p1;
            } else {
                float* of = (float*)outp;
                size_t base = (size_t)row * DMODEL + col;
                *(float2*)(of + base)                       = make_float2(v00, v01);
                *(float2*)(of + base + (size_t)8 * DMODEL)  = make_float2(v10, v11);
            }
        }
    }
}

// ---------------- flash attention (R11 best-measured config) ------------------
// CTA: (b,h,128-query tile), 256 threads = 8 warps x 16 rows, full 64-key
// width per warp, 64-key double-buffered tiles, static 37KB smem, 2 CTAs/SM.
// No-max base-2 softmax, fp16 P via ex2.f16x2, fp16 V, l via ones-mma.
#define AQ 128
#define AROW 144                 // bytes per K/V smem row (128 data + 16 pad)
#define KOFF(s) ((s) * 9216)
#define VOFF(s) (18432 + (s) * 9216)
#define MOFF(s) (36864 + (s) * 256)
#define ASMEM 37376
#define ONE2 0x3C003C00u         // fp16x2 (1.0, 1.0)

__global__ __launch_bounds__(256, 2) void attn_kernel(
    const __nv_bfloat16* __restrict__ Q, const __nv_bfloat16* __restrict__ K,
    const __half* __restrict__ V, const float* __restrict__ mask,
    __nv_bfloat16* __restrict__ ctx)
{
    __shared__ __align__(16) uint8_t smr[ASMEM];
    const uint32_t sb = smem_u32(smr);

    const int tid  = threadIdx.x;
    const int lane = tid & 31;
    const int warp = tid >> 5;

    const int q0 = blockIdx.x * AQ;
    const int h  = blockIdx.y;
    const int b  = blockIdx.z;

    const __nv_bfloat16* Qp = Q + (((size_t)(b * NHEAD + h) * SEQ + q0) * DHEAD);
    const __nv_bfloat16* Kp = K + ((size_t)(b * NHEAD + h) * SEQ) * DHEAD;
    const __half*        Vp = V + ((size_t)(b * NHEAD + h) * SEQ) * DHEAD;
    const float* Mp = mask + (size_t)b * SEQ;

#define APREFETCH(kt, s) do {                                                  \
        const int key0_ = (kt) * 64;                                           \
        _Pragma("unroll")                                                      \
        for (int i_ = 0; i_ < 2; i_++) {                                       \
            int idx_ = tid + i_ * 256;                                         \
            int r_ = idx_ >> 3, q_ = idx_ & 7;                                 \
            cpasync16(sb + KOFF(s) + r_ * AROW + q_ * 16,                      \
                      Kp + (size_t)(key0_ + r_) * DHEAD + q_ * 8);             \
        }                                                                      \
        _Pragma("unroll")                                                      \
        for (int i_ = 0; i_ < 2; i_++) {                                       \
            int idx_ = tid + i_ * 256;                                         \
            int r_ = idx_ >> 3, q_ = idx_ & 7;                                 \
            cpasync16(sb + VOFF(s) + r_ * AROW + q_ * 16,                      \
                      Vp + (size_t)(key0_ + r_) * DHEAD + q_ * 8);             \
        }                                                                      \
        if (tid < 16)                                                          \
            cpasync16(sb + MOFF(s) + tid * 16, Mp + key0_ + tid * 4);          \
        cp_commit();                                                           \
    } while (0)

    APREFETCH(0, 0);

    // ---- Q fragments straight from gmem (bf16 pairs are mma-native)
    uint32_t qf[4][4];
    {
        const int r = warp * 16 + (lane >> 2);
#pragma unroll
        for (int ks = 0; ks < 4; ks++) {
            int k0 = ks * 16 + 2 * (lane & 3);
            qf[ks][0] = *(const uint32_t*)(Qp + (size_t)r * DHEAD + k0);
            qf[ks][1] = *(const uint32_t*)(Qp + (size_t)(r + 8) * DHEAD + k0);
            qf[ks][2] = *(const uint32_t*)(Qp + (size_t)r * DHEAD + k0 + 8);
            qf[ks][3] = *(const uint32_t*)(Qp + (size_t)(r + 8) * DHEAD + k0 + 8);
        }
    }

    float oacc[8][4];
#pragma unroll
    for (int in = 0; in < 8; in++)
#pragma unroll
        for (int k = 0; k < 4; k++) oacc[in][k] = 0.f;
    float lacc[4] = {0.f, 0.f, 0.f, 0.f};   // row-sum accumulator (ones-mma)

    const int lr = lane & 7;
    const uint32_t kloff = (uint32_t)((((lane >> 4) & 1) * 8 + lr) * AROW
                                      + ((lane >> 3) & 1) * 16);
    const uint32_t vlaneoff =
        ((lane & 7) + ((lane & 8) ? 8u : 0u)) * AROW + ((lane & 16) ? 16u : 0u);

    for (int kt = 0; kt < SEQ / 64; kt++) {
        const int bsl = kt & 1;
        cp_wait0();
        __syncthreads();
        if (kt + 1 < SEQ / 64) APREFETCH(kt + 1, 1 - bsl);

        const float*   msk   = (const float*)(smr + MOFF(bsl));
        const uint32_t kbase = sb + KOFF(bsl) + kloff;
        const uint32_t vbase = sb + VOFF(bsl);

        // ---- S = Q @ K^T  (bf16 mma, 16 x 64 per warp)
        float sacc[8][4];
#pragma unroll
        for (int in = 0; in < 8; in++)
#pragma unroll
            for (int k = 0; k < 4; k++) sacc[in][k] = 0.f;

#pragma unroll
        for (int ks = 0; ks < 4; ks++) {
#pragma unroll
            for (int p = 0; p < 4; p++) {
                uint32_t b00, b01, b10, b11;
                ldsm_x4(b00, b01, b10, b11, kbase + p * (16 * AROW) + ks * 32);
                mma_bf16(sacc[2 * p],     qf[ks], b00, b01);
                mma_bf16(sacc[2 * p + 1], qf[ks], b10, b11);
            }
        }

        // ---- mask + no-max base-2 softmax -> fp16 P (one MUFU per pair)
        uint32_t pk[8][2];
#pragma unroll
        for (int in = 0; in < 8; in++) {
            int c = in * 8 + 2 * (lane & 3);
            float mv0 = msk[c], mv1 = msk[c + 1];
            pk[in][0] = ex2_f16x2(sacc[in][0] + mv0, sacc[in][1] + mv1);
            pk[in][1] = ex2_f16x2(sacc[in][2] + mv0, sacc[in][3] + mv1);
        }

        // ---- O += P @ V (f16 mma); l += P @ ones (constant B fragment)
#pragma unroll
        for (int ks = 0; ks < 4; ks++) {
            uint32_t a[4] = { pk[2 * ks][0], pk[2 * ks][1],
                              pk[2 * ks + 1][0], pk[2 * ks + 1][1] };
            mma_f16(lacc, a, ONE2, ONE2);
            uint32_t vk = vbase + (uint32_t)(ks * 16) * AROW + vlaneoff;
#pragma unroll
            for (int gi = 0; gi < 4; gi++) {
                uint32_t b0a, b1a, b0b, b1b;
                ldsm_x4_t(b0a, b1a, b0b, b1b, vk + gi * 32);
                mma_f16(oacc[2 * gi],     a, b0a, b1a);
                mma_f16(oacc[2 * gi + 1], a, b0b, b1b);
            }
        }
    }

    // ---- finalize: /l, write ctx bf16 [B,S,D]
    {
        const int rp = warp * 16 + (lane >> 2);
        const float il0 = 1.f / lacc[0];   // row rp sum
        const float il1 = 1.f / lacc[2];   // row rp+8 sum
#pragma unroll
        for (int in = 0; in < 8; in++) {
            int c = in * 8 + 2 * (lane & 3);
            size_t base = ((size_t)b * SEQ + q0 + rp) * DMODEL + h * DHEAD + c;
            *(uint32_t*)(ctx + base) =
                pack_bf16(oacc[in][0] * il0, oacc[in][1] * il0);
            *(uint32_t*)(ctx + base + (size_t)8 * DMODEL) =
                pack_bf16(oacc[in][2] * il1, oacc[in][3] * il1);
        }
    }
}

// ---------------- residual + LayerNorm ---------------------------------------
__global__ __launch_bounds__(256) void ln_kernel(
    const float* __restrict__ hbuf, const float* __restrict__ x,
    const float* __restrict__ gamma, const float* __restrict__ beta,
    float* __restrict__ out)
{
    const int row = blockIdx.x;
    const int tid = threadIdx.x;
    const int lane = tid & 31, warp = tid >> 5;

    const float4* hp = (const float4*)(hbuf + (size_t)row * DMODEL);
    const float4* xp = (const float4*)(x + (size_t)row * DMODEL);
    float4 hv = hp[tid], xv = xp[tid];
    float4 y = make_float4(hv.x + xv.x, hv.y + xv.y, hv.z + xv.z, hv.w + xv.w);

    float s  = y.x + y.y + y.z + y.w;
    float sq = y.x * y.x + y.y * y.y + y.z * y.z + y.w * y.w;
#pragma unroll
    for (int o = 16; o; o >>= 1) {
        s  += __shfl_xor_sync(0xffffffffu, s, o);
        sq += __shfl_xor_sync(0xffffffffu, sq, o);
    }
    __shared__ float ss[8], ssq[8];
    if (lane == 0) { ss[warp] = s; ssq[warp] = sq; }
    __syncthreads();
    if (warp == 0) {
        s  = (lane < 8) ? ss[lane]  : 0.f;
        sq = (lane < 8) ? ssq[lane] : 0.f;
#pragma unroll
        for (int o = 4; o; o >>= 1) {
            s  += __shfl_xor_sync(0xffffffffu, s, o);
            sq += __shfl_xor_sync(0xffffffffu, sq, o);
        }
        if (lane == 0) { ss[0] = s; ssq[0] = sq; }
    }
    __syncthreads();
    s = ss[0]; sq = ssq[0];

    const float mu   = s * (1.f / DMODEL);
    const float var  = sq * (1.f / DMODEL) - mu * mu;
    const float rstd = rsqrtf(var + 1e-12f);

    float4 g = ((const float4*)gamma)[tid];
    float4 bt = ((const float4*)beta)[tid];
    float4 o;
    o.x = (y.x - mu) * rstd * g.x + bt.x;
    o.y = (y.y - mu) * rstd * g.y + bt.y;
    o.z = (y.z - mu) * rstd * g.z + bt.z;
    o.w = (y.w - mu) * rstd * g.w + bt.w;
    ((float4*)(out + (size_t)row * DMODEL))[tid] = o;
}

// ---------------- launch ------------------------------------------------------
extern "C" void kernel_launch(void* const* d_in, const int* in_sizes, int n_in,
                              void* d_out, int out_size)
{
    const float* x    = (const float*)d_in[0];
    const float* mask = (const float*)d_in[1];
    const float* Wq   = (const float*)d_in[2];
    const float* bq   = (const float*)d_in[3];
    const float* Wk   = (const float*)d_in[4];
    const float* bk   = (const float*)d_in[5];
    const float* Wv   = (const float*)d_in[6];
    const float* bv   = (const float*)d_in[7];
    const float* Wo   = (const float*)d_in[8];
    const float* bo   = (const float*)d_in[9];
    const float* gam  = (const float*)d_in[10];
    const float* bet  = (const float*)d_in[11];
    float* out = (float*)d_out;

    __nv_bfloat16 *pxb, *pQ, *pK, *pC, *pWt;
    __half *pV;
    float *pH, *pM;
    cudaGetSymbolAddress((void**)&pxb, g_xb);
    cudaGetSymbolAddress((void**)&pQ,  g_Qb);
    cudaGetSymbolAddress((void**)&pK,  g_Kb);
    cudaGetSymbolAddress((void**)&pV,  g_Vh);
    cudaGetSymbolAddress((void**)&pC,  g_ctxb);
    cudaGetSymbolAddress((void**)&pWt, g_Wtb);
    cudaGetSymbolAddress((void**)&pH,  g_h);
    cudaGetSymbolAddress((void**)&pM,  g_msc);
    __nv_bfloat16* Wto = pWt + (size_t)3 * DMODEL * DMODEL;

    cvt_kernel<<<MTOT * DMODEL / 4 / 256, 256>>>(x, (__nv_bfloat162*)pxb, mask, pM);
    tr_kernel<<<dim3(32, 32, 4), dim3(32, 8)>>>(Wq, Wk, Wv, Wo, pWt);

    const float qsc = 0.125f * 1.4426950408889634f;   // fold log2e into Q

    // fused QKV: grid.z picks weight/bias/output (z==2 emits fp16 V)
    gemm_bf16<<<dim3(DMODEL / GBN, MTOT / GBM, 3), 256>>>(
        pxb, pWt, bq, bk, bv, pQ, pK, pV, 1, qsc);

    attn_kernel<<<dim3(SEQ / AQ, NHEAD, BATCH), 256>>>(pQ, pK, pV, pM, pC);

    // O-projection (grid.z=1, weight slot 0 = Wto)
    gemm_bf16<<<dim3(DMODEL / GBN, MTOT / GBM, 1), 256>>>(
        pC, Wto, bo, bo, bo, pH, pH, pH, 0, 1.0f);

    ln_kernel<<<MTOT, 256>>>(pH, x, gam, bet, out);
}

// round 17
// speedup vs baseline: 1.0858x; 1.0150x over previous
#include <cuda_runtime.h>
#include <cuda_bf16.h>
#include <cuda_fp16.h>
#include <cstdint>

#define BATCH 4
#define SEQ   2048
#define DMODEL 1024
#define NHEAD 16
#define DHEAD 64
#define MTOT  (BATCH*SEQ)   // 8192

// ---------------- scratch (static device globals; no runtime alloc) ----------
__device__ __nv_bfloat16 g_xb [MTOT*DMODEL];            // x in bf16
__device__ __nv_bfloat16 g_Qb [BATCH*NHEAD*SEQ*DHEAD];  // [B,H,S,DH] bf16
__device__ __nv_bfloat16 g_Kb [BATCH*NHEAD*SEQ*DHEAD];  // bf16
__device__ __half        g_Vh [BATCH*NHEAD*SEQ*DHEAD];  // fp16 (for f16 PV mma)
__device__ __nv_bfloat16 g_ctxb[MTOT*DMODEL];           // attention out, bf16
__device__ __nv_bfloat16 g_Wtb[4*DMODEL*DMODEL];        // transposed bf16 weights
__device__ __nv_bfloat16 g_hb [MTOT*DMODEL];            // O-proj out, bf16
__device__ __half        g_msc[BATCH*SEQ];              // mask * log2(e), fp16

// ---------------- low-level helpers ------------------------------------------
__device__ __forceinline__ uint32_t smem_u32(const void* p) {
    uint32_t a;
    asm("{ .reg .u64 t; cvta.to.shared.u64 t, %1; cvt.u32.u64 %0, t; }" : "=r"(a) : "l"(p));
    return a;
}
__device__ __forceinline__ void cpasync16(uint32_t dst, const void* src) {
    asm volatile("cp.async.cg.shared.global [%0], [%1], 16;" :: "r"(dst), "l"(src));
}
__device__ __forceinline__ void cp_commit() { asm volatile("cp.async.commit_group;"); }
__device__ __forceinline__ void cp_wait0()  { asm volatile("cp.async.wait_group 0;"); }

// pack two f32 -> f16x2, add f16x2 mask, exp2 both halves (one MUFU op)
__device__ __forceinline__ uint32_t ex2m_f16x2(float lo, float hi, uint32_t m2) {
    uint32_t d;
    asm("cvt.rn.f16x2.f32 %0, %1, %2;" : "=r"(d) : "f"(hi), "f"(lo));
    asm("add.f16x2 %0, %0, %1;" : "+r"(d) : "r"(m2));
    asm("ex2.approx.f16x2 %0, %0;" : "+r"(d));
    return d;
}

__device__ __forceinline__ void mma_bf16(float c[4], const uint32_t a[4],
                                         uint32_t b0, uint32_t b1) {
    asm volatile(
        "mma.sync.aligned.m16n8k16.row.col.f32.bf16.bf16.f32 "
        "{%0,%1,%2,%3}, {%4,%5,%6,%7}, {%8,%9}, {%0,%1,%2,%3};"
        : "+f"(c[0]), "+f"(c[1]), "+f"(c[2]), "+f"(c[3])
        : "r"(a[0]), "r"(a[1]), "r"(a[2]), "r"(a[3]), "r"(b0), "r"(b1));
}
__device__ __forceinline__ void mma_f16(float c[4], const uint32_t a[4],
                                        uint32_t b0, uint32_t b1) {
    asm volatile(
        "mma.sync.aligned.m16n8k16.row.col.f32.f16.f16.f32 "
        "{%0,%1,%2,%3}, {%4,%5,%6,%7}, {%8,%9}, {%0,%1,%2,%3};"
        : "+f"(c[0]), "+f"(c[1]), "+f"(c[2]), "+f"(c[3])
        : "r"(a[0]), "r"(a[1]), "r"(a[2]), "r"(a[3]), "r"(b0), "r"(b1));
}
__device__ __forceinline__ void ldsm_x4(uint32_t& r0, uint32_t& r1,
                                        uint32_t& r2, uint32_t& r3, uint32_t addr) {
    asm volatile("ldmatrix.sync.aligned.m8n8.x4.shared.b16 {%0,%1,%2,%3}, [%4];"
        : "=r"(r0), "=r"(r1), "=r"(r2), "=r"(r3) : "r"(addr));
}
__device__ __forceinline__ void ldsm_x4_t(uint32_t& r0, uint32_t& r1,
                                          uint32_t& r2, uint32_t& r3, uint32_t addr) {
    asm volatile("ldmatrix.sync.aligned.m8n8.x4.trans.shared.b16 {%0,%1,%2,%3}, [%4];"
        : "=r"(r0), "=r"(r1), "=r"(r2), "=r"(r3) : "r"(addr));
}
__device__ __forceinline__ uint32_t pack_bf16(float lo, float hi) {
    __nv_bfloat162 t = __float22bfloat162_rn(make_float2(lo, hi));
    return *reinterpret_cast<uint32_t*>(&t);
}
__device__ __forceinline__ uint32_t pack_f16(float lo, float hi) {
    __half2 t = __floats2half2_rn(lo, hi);
    return *reinterpret_cast<uint32_t*>(&t);
}

// ---------------- fp32 -> bf16 convert (+ fused fp16 mask prescale) -----------
__global__ __launch_bounds__(256) void cvt_kernel(
    const float* __restrict__ x, __nv_bfloat162* __restrict__ o,
    const float* __restrict__ mask, __half2* __restrict__ msc)
{
    size_t i = (size_t)blockIdx.x * 256 + threadIdx.x;   // over float4
    float4 v = ((const float4*)x)[i];
    o[2 * i]     = __float22bfloat162_rn(make_float2(v.x, v.y));
    o[2 * i + 1] = __float22bfloat162_rn(make_float2(v.z, v.w));
    if (i < BATCH * SEQ / 2) {
        const float C = 1.4426950408889634f;
        msc[i] = __floats2half2_rn(mask[2 * i] * C, mask[2 * i + 1] * C);
    }
}

// -------- transpose + convert all 4 weights: W[K][N] fp32 -> Wt[N][K] bf16 ----
__global__ __launch_bounds__(256) void tr_kernel(
    const float* __restrict__ s0, const float* __restrict__ s1,
    const float* __restrict__ s2, const float* __restrict__ s3,
    __nv_bfloat16* __restrict__ dstb)
{
    const float* src = (blockIdx.z == 0) ? s0 : (blockIdx.z == 1) ? s1
                     : (blockIdx.z == 2) ? s2 : s3;
    __nv_bfloat16* dst = dstb + (size_t)blockIdx.z * DMODEL * DMODEL;
    __shared__ float t[32][33];
    int x = blockIdx.x * 32 + threadIdx.x;
    int y = blockIdx.y * 32 + threadIdx.y;
#pragma unroll
    for (int j = 0; j < 32; j += 8)
        t[threadIdx.y + j][threadIdx.x] = src[(size_t)(y + j) * DMODEL + x];
    __syncthreads();
    int x2 = blockIdx.y * 32 + threadIdx.x;
    int y2 = blockIdx.x * 32 + threadIdx.y;
#pragma unroll
    for (int j = 0; j < 32; j += 8)
        dst[(size_t)(y2 + j) * DMODEL + x2] = __float2bfloat16(t[threadIdx.x][threadIdx.y + j]);
}

// ---------------- bf16 GEMM: out = A[M,1024] @ Wt^T + bias --------------------
// R7 shape: BM=BN=128, BK=32, 8 warps (4m x 2n), warp tile 32x64, m16n8k16,
// 2-stage cp.async, static 40KB smem, 2 CTAs/SM. grid.z selects weight/bias/out.
// z==2 (V projection) emits fp16; other outputs emit bf16.
#define GBM 128
#define GBN 128
#define GBK 32
#define GLD 20                 // words per smem row (16 data + 4 pad)
#define GROWB (GLD*4)          // 80 bytes per row
#define GSTG (128*GLD)         // words per half-stage (A or B)

__global__ __launch_bounds__(256, 2) void gemm_bf16(
    const __nv_bfloat16* __restrict__ A, const __nv_bfloat16* __restrict__ Wt3,
    const float* __restrict__ b0p, const float* __restrict__ b1p,
    const float* __restrict__ b2p,
    void* __restrict__ o0p, void* __restrict__ o1p, void* __restrict__ o2p,
    int split_heads, float scale0)
{
    __shared__ __align__(16) uint32_t gsm[4 * GSTG];   // A0,A1,B0,B1 = 40KB
    const uint32_t sb = smem_u32(gsm);

    const int z = blockIdx.z;
    const __nv_bfloat16* Bt = Wt3 + (size_t)z * DMODEL * DMODEL;
    const float* bias = (z == 0) ? b0p : (z == 1) ? b1p : b2p;
    void* outp        = (z == 0) ? o0p : (z == 1) ? o1p : o2p;
    const float oscale = (z == 0) ? scale0 : 1.0f;
    const int fp16out  = (z == 2);

    const int tid  = threadIdx.x;
    const int lane = tid & 31;
    const int warp = tid >> 5;
    const int wm   = warp >> 1;          // 0..3
    const int wn   = warp & 1;           // 0..1
    const int m0   = blockIdx.y * GBM;
    const int n0   = blockIdx.x * GBN;

    const __nv_bfloat16* Abase = A  + (size_t)m0 * DMODEL;
    const __nv_bfloat16* Bbase = Bt + (size_t)n0 * DMODEL;

    const int lr = lane & 7;
    const uint32_t aoff = (uint32_t)((((lane >> 3) & 1) * 8 + lr) * GROWB
                                     + ((lane >> 4) & 1) * 16);
    const uint32_t boff = (uint32_t)((((lane >> 4) & 1) * 8 + lr) * GROWB
                                     + ((lane >> 3) & 1) * 16);

    float acc[2][8][4];
#pragma unroll
    for (int im = 0; im < 2; im++)
#pragma unroll
        for (int in = 0; in < 8; in++)
#pragma unroll
            for (int k = 0; k < 4; k++) acc[im][in][k] = 0.f;

#define GLOAD(c, s) do {                                                       \
        _Pragma("unroll")                                                      \
        for (int i_ = 0; i_ < 2; i_++) {                                       \
            int idx_ = tid + i_ * 256;                                         \
            int r_ = idx_ >> 2, q_ = idx_ & 3;                                 \
            cpasync16(sb + ((s) * GSTG + r_ * GLD + q_ * 4) * 4,               \
                      Abase + (size_t)r_ * DMODEL + (c) * GBK + q_ * 8);       \
        }                                                                      \
        _Pragma("unroll")                                                      \
        for (int i_ = 0; i_ < 2; i_++) {                                       \
            int idx_ = tid + i_ * 256;                                         \
            int r_ = idx_ >> 2, q_ = idx_ & 3;                                 \
            cpasync16(sb + ((2 + (s)) * GSTG + (r_ * GLD + q_ * 4)) * 4,       \
                      Bbase + (size_t)r_ * DMODEL + (c) * GBK + q_ * 8);       \
        }                                                                      \
        cp_commit();                                                           \
    } while (0)

    GLOAD(0, 0);
    const int NCH = DMODEL / GBK;   // 32
    for (int c = 0; c < NCH; c++) {
        const int bsl = c & 1;
        cp_wait0();
        __syncthreads();
        if (c + 1 < NCH) GLOAD(c + 1, 1 - bsl);

        const uint32_t abase = sb + (uint32_t)(bsl * GSTG * 4)
                             + (uint32_t)(wm * 32) * GROWB + aoff;
        const uint32_t bbase = sb + (uint32_t)((2 + bsl) * GSTG * 4)
                             + (uint32_t)(wn * 64) * GROWB + boff;

#pragma unroll
        for (int ks = 0; ks < 2; ks++) {
            uint32_t a[2][4];
            ldsm_x4(a[0][0], a[0][1], a[0][2], a[0][3], abase + ks * 32);
            ldsm_x4(a[1][0], a[1][1], a[1][2], a[1][3], abase + 16 * GROWB + ks * 32);
#pragma unroll
            for (int p = 0; p < 4; p++) {
                uint32_t b00, b01, b10, b11;
                ldsm_x4(b00, b01, b10, b11, bbase + p * 16 * GROWB + ks * 32);
                mma_bf16(acc[0][2 * p],     a[0], b00, b01);
                mma_bf16(acc[0][2 * p + 1], a[0], b10, b11);
                mma_bf16(acc[1][2 * p],     a[1], b00, b01);
                mma_bf16(acc[1][2 * p + 1], a[1], b10, b11);
            }
        }
        __syncthreads();
    }

    // epilogue
#pragma unroll
    for (int im = 0; im < 2; im++) {
#pragma unroll
        for (int in = 0; in < 8; in++) {
            int row = m0 + wm * 32 + im * 16 + (lane >> 2);
            int col = n0 + wn * 64 + in * 8 + 2 * (lane & 3);
            float b0 = bias[col], b1 = bias[col + 1];
            float v00 = (acc[im][in][0] + b0) * oscale;
            float v01 = (acc[im][in][1] + b1) * oscale;
            float v10 = (acc[im][in][2] + b0) * oscale;
            float v11 = (acc[im][in][3] + b1) * oscale;
            if (split_heads) {
                uint16_t* ob = (uint16_t*)outp;
                int bb = row >> 11, s = row & (SEQ - 1);
                int hh = col >> 6,  d = col & 63;
                size_t base = (((size_t)(bb * NHEAD + hh) * SEQ + s) * DHEAD + d);
                uint32_t p0 = fp16out ? pack_f16(v00, v01) : pack_bf16(v00, v01);
                uint32_t p1 = fp16out ? pack_f16(v10, v11) : pack_bf16(v10, v11);
                *(uint32_t*)(ob + base)              = p0;
                *(uint32_t*)(ob + base + 8 * DHEAD)  = p1;
            } else {
                // O-projection path: emit bf16 (residual+LN reads bf16)
                uint16_t* ob = (uint16_t*)outp;
                size_t base = (size_t)row * DMODEL + col;
                *(uint32_t*)(ob + base)                      = pack_bf16(v00, v01);
                *(uint32_t*)(ob + base + (size_t)8 * DMODEL) = pack_bf16(v10, v11);
            }
        }
    }
}

// ---------------- flash attention (R11 best-measured config) ------------------
// CTA: (b,h,128-query tile), 256 threads = 8 warps x 16 rows, full 64-key
// width per warp, 64-key double-buffered tiles, static 37KB smem, 2 CTAs/SM.
// No-max base-2 softmax; mask added in fp16 (HADD2); fp16 P via ex2.f16x2;
// fp16 V; l via ones-mma.
#define AQ 128
#define AROW 144                 // bytes per K/V smem row (128 data + 16 pad)
#define KOFF(s) ((s) * 9216)
#define VOFF(s) (18432 + (s) * 9216)
#define MOFF(s) (36864 + (s) * 256)
#define ASMEM 37376
#define ONE2 0x3C003C00u         // fp16x2 (1.0, 1.0)

__global__ __launch_bounds__(256, 2) void attn_kernel(
    const __nv_bfloat16* __restrict__ Q, const __nv_bfloat16* __restrict__ K,
    const __half* __restrict__ V, const __half* __restrict__ mask,
    __nv_bfloat16* __restrict__ ctx)
{
    __shared__ __align__(16) uint8_t smr[ASMEM];
    const uint32_t sb = smem_u32(smr);

    const int tid  = threadIdx.x;
    const int lane = tid & 31;
    const int warp = tid >> 5;

    const int q0 = blockIdx.x * AQ;
    const int h  = blockIdx.y;
    const int b  = blockIdx.z;

    const __nv_bfloat16* Qp = Q + (((size_t)(b * NHEAD + h) * SEQ + q0) * DHEAD);
    const __nv_bfloat16* Kp = K + ((size_t)(b * NHEAD + h) * SEQ) * DHEAD;
    const __half*        Vp = V + ((size_t)(b * NHEAD + h) * SEQ) * DHEAD;
    const __half*        Mp = mask + (size_t)b * SEQ;

#define APREFETCH(kt, s) do {                                                  \
        const int key0_ = (kt) * 64;                                           \
        _Pragma("unroll")                                                      \
        for (int i_ = 0; i_ < 2; i_++) {                                       \
            int idx_ = tid + i_ * 256;                                         \
            int r_ = idx_ >> 3, q_ = idx_ & 7;                                 \
            cpasync16(sb + KOFF(s) + r_ * AROW + q_ * 16,                      \
                      Kp + (size_t)(key0_ + r_) * DHEAD + q_ * 8);             \
        }                                                                      \
        _Pragma("unroll")                                                      \
        for (int i_ = 0; i_ < 2; i_++) {                                       \
            int idx_ = tid + i_ * 256;                                         \
            int r_ = idx_ >> 3, q_ = idx_ & 7;                                 \
            cpasync16(sb + VOFF(s) + r_ * AROW + q_ * 16,                      \
                      Vp + (size_t)(key0_ + r_) * DHEAD + q_ * 8);             \
        }                                                                      \
        if (tid < 8)                                                           \
            cpasync16(sb + MOFF(s) + tid * 16, Mp + key0_ + tid * 8);          \
        cp_commit();                                                           \
    } while (0)

    APREFETCH(0, 0);

    // ---- Q fragments straight from gmem (bf16 pairs are mma-native)
    uint32_t qf[4][4];
    {
        const int r = warp * 16 + (lane >> 2);
#pragma unroll
        for (int ks = 0; ks < 4; ks++) {
            int k0 = ks * 16 + 2 * (lane & 3);
            qf[ks][0] = *(const uint32_t*)(Qp + (size_t)r * DHEAD + k0);
            qf[ks][1] = *(const uint32_t*)(Qp + (size_t)(r + 8) * DHEAD + k0);
            qf[ks][2] = *(const uint32_t*)(Qp + (size_t)r * DHEAD + k0 + 8);
            qf[ks][3] = *(const uint32_t*)(Qp + (size_t)(r + 8) * DHEAD + k0 + 8);
        }
    }

    float oacc[8][4];
#pragma unroll
    for (int in = 0; in < 8; in++)
#pragma unroll
        for (int k = 0; k < 4; k++) oacc[in][k] = 0.f;
    float lacc[4] = {0.f, 0.f, 0.f, 0.f};   // row-sum accumulator (ones-mma)

    const int lr = lane & 7;
    const uint32_t kloff = (uint32_t)((((lane >> 4) & 1) * 8 + lr) * AROW
                                      + ((lane >> 3) & 1) * 16);
    const uint32_t vlaneoff =
        ((lane & 7) + ((lane & 8) ? 8u : 0u)) * AROW + ((lane & 16) ? 16u : 0u);

    for (int kt = 0; kt < SEQ / 64; kt++) {
        const int bsl = kt & 1;
        cp_wait0();
        __syncthreads();
        if (kt + 1 < SEQ / 64) APREFETCH(kt + 1, 1 - bsl);

        const uint8_t* mskb  = smr + MOFF(bsl);
        const uint32_t kbase = sb + KOFF(bsl) + kloff;
        const uint32_t vbase = sb + VOFF(bsl);

        // ---- S = Q @ K^T  (bf16 mma, 16 x 64 per warp)
        float sacc[8][4];
#pragma unroll
        for (int in = 0; in < 8; in++)
#pragma unroll
            for (int k = 0; k < 4; k++) sacc[in][k] = 0.f;

#pragma unroll
        for (int ks = 0; ks < 4; ks++) {
#pragma unroll
            for (int p = 0; p < 4; p++) {
                uint32_t b00, b01, b10, b11;
                ldsm_x4(b00, b01, b10, b11, kbase + p * (16 * AROW) + ks * 32);
                mma_bf16(sacc[2 * p],     qf[ks], b00, b01);
                mma_bf16(sacc[2 * p + 1], qf[ks], b10, b11);
            }
        }

        // ---- fp16 mask add + no-max base-2 softmax -> fp16 P
        uint32_t pk[8][2];
#pragma unroll
        for (int in = 0; in < 8; in++) {
            int c = in * 8 + 2 * (lane & 3);
            uint32_t mv2 = *(const uint32_t*)(mskb + c * 2);   // half2 (m[c],m[c+1])
            pk[in][0] = ex2m_f16x2(sacc[in][0], sacc[in][1], mv2);
            pk[in][1] = ex2m_f16x2(sacc[in][2], sacc[in][3], mv2);
        }

        // ---- O += P @ V (f16 mma); l += P @ ones (constant B fragment)
#pragma unroll
        for (int ks = 0; ks < 4; ks++) {
            uint32_t a[4] = { pk[2 * ks][0], pk[2 * ks][1],
                              pk[2 * ks + 1][0], pk[2 * ks + 1][1] };
            mma_f16(lacc, a, ONE2, ONE2);
            uint32_t vk = vbase + (uint32_t)(ks * 16) * AROW + vlaneoff;
#pragma unroll
            for (int gi = 0; gi < 4; gi++) {
                uint32_t b0a, b1a, b0b, b1b;
                ldsm_x4_t(b0a, b1a, b0b, b1b, vk + gi * 32);
                mma_f16(oacc[2 * gi],     a, b0a, b1a);
                mma_f16(oacc[2 * gi + 1], a, b0b, b1b);
            }
        }
    }

    // ---- finalize: /l, write ctx bf16 [B,S,D]
    {
        const int rp = warp * 16 + (lane >> 2);
        const float il0 = 1.f / lacc[0];   // row rp sum
        const float il1 = 1.f / lacc[2];   // row rp+8 sum
#pragma unroll
        for (int in = 0; in < 8; in++) {
            int c = in * 8 + 2 * (lane & 3);
            size_t base = ((size_t)b * SEQ + q0 + rp) * DMODEL + h * DHEAD + c;
            *(uint32_t*)(ctx + base) =
                pack_bf16(oacc[in][0] * il0, oacc[in][1] * il0);
            *(uint32_t*)(ctx + base + (size_t)8 * DMODEL) =
                pack_bf16(oacc[in][2] * il1, oacc[in][3] * il1);
        }
    }
}

// ---------------- residual + LayerNorm (bf16 h input) --------------------------
__global__ __launch_bounds__(256) void ln_kernel(
    const __nv_bfloat16* __restrict__ hbuf, const float* __restrict__ x,
    const float* __restrict__ gamma, const float* __restrict__ beta,
    float* __restrict__ out)
{
    const int row = blockIdx.x;
    const int tid = threadIdx.x;
    const int lane = tid & 31, warp = tid >> 5;

    const __nv_bfloat162* hp = (const __nv_bfloat162*)(hbuf + (size_t)row * DMODEL);
    const float4* xp = (const float4*)(x + (size_t)row * DMODEL);
    float2 h0 = __bfloat1622float2(hp[2 * tid]);
    float2 h1 = __bfloat1622float2(hp[2 * tid + 1]);
    float4 xv = xp[tid];
    float4 y = make_float4(h0.x + xv.x, h0.y + xv.y, h1.x + xv.z, h1.y + xv.w);

    float s  = y.x + y.y + y.z + y.w;
    float sq = y.x * y.x + y.y * y.y + y.z * y.z + y.w * y.w;
#pragma unroll
    for (int o = 16; o; o >>= 1) {
        s  += __shfl_xor_sync(0xffffffffu, s, o);
        sq += __shfl_xor_sync(0xffffffffu, sq, o);
    }
    __shared__ float ss[8], ssq[8];
    if (lane == 0) { ss[warp] = s; ssq[warp] = sq; }
    __syncthreads();
    if (warp == 0) {
        s  = (lane < 8) ? ss[lane]  : 0.f;
        sq = (lane < 8) ? ssq[lane] : 0.f;
#pragma unroll
        for (int o = 4; o; o >>= 1) {
            s  += __shfl_xor_sync(0xffffffffu, s, o);
            sq += __shfl_xor_sync(0xffffffffu, sq, o);
        }
        if (lane == 0) { ss[0] = s; ssq[0] = sq; }
    }
    __syncthreads();
    s = ss[0]; sq = ssq[0];

    const float mu   = s * (1.f / DMODEL);
    const float var  = sq * (1.f / DMODEL) - mu * mu;
    const float rstd = rsqrtf(var + 1e-12f);

    float4 g = ((const float4*)gamma)[tid];
    float4 bt = ((const float4*)beta)[tid];
    float4 o;
    o.x = (y.x - mu) * rstd * g.x + bt.x;
    o.y = (y.y - mu) * rstd * g.y + bt.y;
    o.z = (y.z - mu) * rstd * g.z + bt.z;
    o.w = (y.w - mu) * rstd * g.w + bt.w;
    ((float4*)(out + (size_t)row * DMODEL))[tid] = o;
}

// ---------------- launch ------------------------------------------------------
extern "C" void kernel_launch(void* const* d_in, const int* in_sizes, int n_in,
                              void* d_out, int out_size)
{
    const float* x    = (const float*)d_in[0];
    const float* mask = (const float*)d_in[1];
    const float* Wq   = (const float*)d_in[2];
    const float* bq   = (const float*)d_in[3];
    const float* Wk   = (const float*)d_in[4];
    const float* bk   = (const float*)d_in[5];
    const float* Wv   = (const float*)d_in[6];
    const float* bv   = (const float*)d_in[7];
    const float* Wo   = (const float*)d_in[8];
    const float* bo   = (const float*)d_in[9];
    const float* gam  = (const float*)d_in[10];
    const float* bet  = (const float*)d_in[11];
    float* out = (float*)d_out;

    __nv_bfloat16 *pxb, *pQ, *pK, *pC, *pWt, *pH;
    __half *pV, *pM;
    cudaGetSymbolAddress((void**)&pxb, g_xb);
    cudaGetSymbolAddress((void**)&pQ,  g_Qb);
    cudaGetSymbolAddress((void**)&pK,  g_Kb);
    cudaGetSymbolAddress((void**)&pV,  g_Vh);
    cudaGetSymbolAddress((void**)&pC,  g_ctxb);
    cudaGetSymbolAddress((void**)&pWt, g_Wtb);
    cudaGetSymbolAddress((void**)&pH,  g_hb);
    cudaGetSymbolAddress((void**)&pM,  g_msc);
    __nv_bfloat16* Wto = pWt + (size_t)3 * DMODEL * DMODEL;

    cvt_kernel<<<MTOT * DMODEL / 4 / 256, 256>>>(x, (__nv_bfloat162*)pxb, mask, (__half2*)pM);
    tr_kernel<<<dim3(32, 32, 4), dim3(32, 8)>>>(Wq, Wk, Wv, Wo, pWt);

    const float qsc = 0.125f * 1.4426950408889634f;   // fold log2e into Q

    // fused QKV: grid.z picks weight/bias/output (z==2 emits fp16 V)
    gemm_bf16<<<dim3(DMODEL / GBN, MTOT / GBM, 3), 256>>>(
        pxb, pWt, bq, bk, bv, pQ, pK, pV, 1, qsc);

    attn_kernel<<<dim3(SEQ / AQ, NHEAD, BATCH), 256>>>(pQ, pK, pV, pM, pC);

    // O-projection (grid.z=1, weight slot 0 = Wto, bf16 output)
    gemm_bf16<<<dim3(DMODEL / GBN, MTOT / GBM, 1), 256>>>(
        pC, Wto, bo, bo, bo, pH, pH, pH, 0, 1.0f);

    ln_kernel<<<MTOT, 256>>>(pH, x, gam, bet, out);
}